// round 4
// baseline (speedup 1.0000x reference)
#include <cuda_runtime.h>
#include <cuda_bf16.h>

// Problem constants
#define BATCH 64
#define SEQ   197
#define EDIM  768
#define NH    12
#define HD    64
#define MROWS (BATCH * SEQ)          // 12608
#define PERB  (SEQ * EDIM)           // 151296 floats per batch
#define PERH  (SEQ * HD)             // 12608 floats per head-chunk

// Intermediate buffers (static device globals: no runtime allocation)
__device__ float g_Q[MROWS * EDIM];
__device__ float g_K[MROWS * EDIM];
__device__ float g_V[MROWS * EDIM];
__device__ float g_AO[MROWS * EDIM];

// ---------------------------------------------------------------------------
// tf32 helpers
// ---------------------------------------------------------------------------
__device__ __forceinline__ unsigned f2tf32(float v) {
    unsigned r;
    asm("cvt.rna.tf32.f32 %0, %1;" : "=r"(r) : "f"(v));
    return r;
}

__device__ __forceinline__ void mma_tf32(
    float& d0, float& d1, float& d2, float& d3,
    unsigned a0, unsigned a1, unsigned a2, unsigned a3,
    unsigned b0, unsigned b1)
{
    asm volatile(
        "mma.sync.aligned.m16n8k8.row.col.f32.tf32.tf32.f32 "
        "{%0,%1,%2,%3}, {%4,%5,%6,%7}, {%8,%9}, {%0,%1,%2,%3};\n"
        : "+f"(d0), "+f"(d1), "+f"(d2), "+f"(d3)
        : "r"(a0), "r"(a1), "r"(a2), "r"(a3), "r"(b0), "r"(b1));
}

// ---------------------------------------------------------------------------
// tf32 3x-split NT GEMM: C[M,N] = A[M,K] @ B[N,K]^T + bias[N]
// M=12608, N=768, K=768. BM=BN=128, BK=16, 256 threads (8 warps: 2 along M
// x 4 along N; warp tile 64x32 = 4x4 m16n8 tiles). 3xTF32: A=Ahi+Alo,
// B=Bhi+Blo; acc += Ahi*Bhi + Ahi*Blo + Alo*Bhi  (near-fp32 precision).
// smem stride 20 makes all fragment LDS bank-conflict-free.
// ---------------------------------------------------------------------------
#define BKP 20

__device__ __forceinline__ void gemm_tf32_body(
    const float* __restrict__ A,
    const float* __restrict__ B,
    const float* __restrict__ bias,
    float* __restrict__ C)
{
    __shared__ unsigned As_hi[128 * BKP];
    __shared__ unsigned As_lo[128 * BKP];
    __shared__ unsigned Bs_hi[128 * BKP];
    __shared__ unsigned Bs_lo[128 * BKP];

    const int tid  = threadIdx.x;
    const int warp = tid >> 5;
    const int lane = tid & 31;
    const int g    = lane >> 2;        // 0..7
    const int c    = lane & 3;         // 0..3
    const int warpM = warp & 1;        // 0..1  -> rows warpM*64
    const int warpN = warp >> 1;       // 0..3  -> cols warpN*32

    const int bm = blockIdx.y * 128;
    const int bn = blockIdx.x * 128;

    // Global-load assignment: 512 float4 per tile per matrix, 2 per thread.
    const int ldRow = tid >> 1;                 // 0..127
    const int ldK0  = (tid & 1) * 8;            // 0 or 8 (two float4 -> 8 floats)
    const int aRowG = bm + ldRow;
    const bool aValid = (aRowG < MROWS);
    const int bRowG = bn + ldRow;               // N=768, always valid

    float acc[4][4][4];
    #pragma unroll
    for (int mt = 0; mt < 4; mt++)
        #pragma unroll
        for (int nt = 0; nt < 4; nt++)
            #pragma unroll
            for (int r = 0; r < 4; r++)
                acc[mt][nt][r] = 0.0f;

    // prefetch first tile
    float4 ra0, ra1, rb0, rb1;
    {
        const float* ap = A + (size_t)aRowG * EDIM + ldK0;
        const float* bp = B + (size_t)bRowG * EDIM + ldK0;
        ra0 = aValid ? *(const float4*)(ap)     : make_float4(0,0,0,0);
        ra1 = aValid ? *(const float4*)(ap + 4) : make_float4(0,0,0,0);
        rb0 = *(const float4*)(bp);
        rb1 = *(const float4*)(bp + 4);
    }

    const int kTiles = EDIM / 16;   // 48
    for (int kt = 0; kt < kTiles; kt++) {
        __syncthreads();
        // split + store to smem
        {
            unsigned* ah = As_hi + ldRow * BKP + ldK0;
            unsigned* al = As_lo + ldRow * BKP + ldK0;
            unsigned* bh = Bs_hi + ldRow * BKP + ldK0;
            unsigned* bl = Bs_lo + ldRow * BKP + ldK0;
            float av[8] = {ra0.x, ra0.y, ra0.z, ra0.w, ra1.x, ra1.y, ra1.z, ra1.w};
            float bv[8] = {rb0.x, rb0.y, rb0.z, rb0.w, rb1.x, rb1.y, rb1.z, rb1.w};
            #pragma unroll
            for (int j = 0; j < 8; j++) {
                unsigned h = f2tf32(av[j]);
                ah[j] = h;
                al[j] = f2tf32(av[j] - __uint_as_float(h));
                h = f2tf32(bv[j]);
                bh[j] = h;
                bl[j] = f2tf32(bv[j] - __uint_as_float(h));
            }
        }
        __syncthreads();

        // prefetch next tile while computing this one
        if (kt + 1 < kTiles) {
            const int k0n = (kt + 1) * 16;
            const float* ap = A + (size_t)aRowG * EDIM + k0n + ldK0;
            const float* bp = B + (size_t)bRowG * EDIM + k0n + ldK0;
            ra0 = aValid ? *(const float4*)(ap)     : make_float4(0,0,0,0);
            ra1 = aValid ? *(const float4*)(ap + 4) : make_float4(0,0,0,0);
            rb0 = *(const float4*)(bp);
            rb1 = *(const float4*)(bp + 4);
        }

        #pragma unroll
        for (int ks = 0; ks < 2; ks++) {
            const int kk = ks * 8;
            unsigned ah[4][4], al[4][4], bh[4][2], bl[4][2];
            #pragma unroll
            for (int mt = 0; mt < 4; mt++) {
                const int r0 = warpM * 64 + mt * 16 + g;
                ah[mt][0] = As_hi[(r0    ) * BKP + kk + c];
                ah[mt][1] = As_hi[(r0 + 8) * BKP + kk + c];
                ah[mt][2] = As_hi[(r0    ) * BKP + kk + c + 4];
                ah[mt][3] = As_hi[(r0 + 8) * BKP + kk + c + 4];
                al[mt][0] = As_lo[(r0    ) * BKP + kk + c];
                al[mt][1] = As_lo[(r0 + 8) * BKP + kk + c];
                al[mt][2] = As_lo[(r0    ) * BKP + kk + c + 4];
                al[mt][3] = As_lo[(r0 + 8) * BKP + kk + c + 4];
            }
            #pragma unroll
            for (int nt = 0; nt < 4; nt++) {
                const int n0 = warpN * 32 + nt * 8 + g;
                bh[nt][0] = Bs_hi[n0 * BKP + kk + c];
                bh[nt][1] = Bs_hi[n0 * BKP + kk + c + 4];
                bl[nt][0] = Bs_lo[n0 * BKP + kk + c];
                bl[nt][1] = Bs_lo[n0 * BKP + kk + c + 4];
            }
            #pragma unroll
            for (int mt = 0; mt < 4; mt++)
                #pragma unroll
                for (int nt = 0; nt < 4; nt++) {
                    float* d = acc[mt][nt];
                    mma_tf32(d[0], d[1], d[2], d[3],
                             ah[mt][0], ah[mt][1], ah[mt][2], ah[mt][3],
                             bh[nt][0], bh[nt][1]);
                    mma_tf32(d[0], d[1], d[2], d[3],
                             ah[mt][0], ah[mt][1], ah[mt][2], ah[mt][3],
                             bl[nt][0], bl[nt][1]);
                    mma_tf32(d[0], d[1], d[2], d[3],
                             al[mt][0], al[mt][1], al[mt][2], al[mt][3],
                             bh[nt][0], bh[nt][1]);
                }
        }
    }

    // epilogue: C[row][col] = acc + bias
    #pragma unroll
    for (int mt = 0; mt < 4; mt++) {
        const int row0 = bm + warpM * 64 + mt * 16 + g;
        const int row1 = row0 + 8;
        #pragma unroll
        for (int nt = 0; nt < 4; nt++) {
            const int col = bn + warpN * 32 + nt * 8 + 2 * c;
            const float b0 = bias[col];
            const float b1 = bias[col + 1];
            if (row0 < MROWS) {
                float2 v = make_float2(acc[mt][nt][0] + b0, acc[mt][nt][1] + b1);
                *(float2*)(C + (size_t)row0 * EDIM + col) = v;
            }
            if (row1 < MROWS) {
                float2 v = make_float2(acc[mt][nt][2] + b0, acc[mt][nt][3] + b1);
                *(float2*)(C + (size_t)row1 * EDIM + col) = v;
            }
        }
    }
}

__global__ __launch_bounds__(256, 1) void qkv_gemm_kernel(
    const float* __restrict__ x,
    const float* __restrict__ Wq, const float* __restrict__ bq,
    const float* __restrict__ Wk, const float* __restrict__ bk,
    const float* __restrict__ Wv, const float* __restrict__ bv)
{
    const float* W;
    const float* bias;
    float* C;
    if (blockIdx.z == 0)      { W = Wq; bias = bq; C = g_Q; }
    else if (blockIdx.z == 1) { W = Wk; bias = bk; C = g_K; }
    else                      { W = Wv; bias = bv; C = g_V; }
    gemm_tf32_body(x, W, bias, C);
}

__global__ __launch_bounds__(256, 1) void proj_gemm_kernel(
    const float* __restrict__ Wp, const float* __restrict__ bp,
    float* __restrict__ out)
{
    gemm_tf32_body(g_AO, Wp, bp, out);
}

// ---------------------------------------------------------------------------
// Attention: 2 CTAs per (b, h), each takes alternate groups of 8 Q rows.
// K,V in smem at row stride 68 (float4-conflict-free). fp32 SIMT math.
// Quirk: softmax first, then divide by sqrt(E) (folded into row scale).
// ---------------------------------------------------------------------------
#define KVS 68
#define EROW_STRIDE 208
#define ATTN_SMEM_FLOATS (SEQ * KVS * 2 + 8 * HD + 8 * EROW_STRIDE)
#define ATTN_SMEM_BYTES  (ATTN_SMEM_FLOATS * 4)

__global__ __launch_bounds__(256, 1) void attn_kernel()
{
    extern __shared__ float sm[];
    float* Ks = sm;                          // [197][68]
    float* Vs = Ks + SEQ * KVS;              // [197][68]
    float* qs = Vs + SEQ * KVS;              // [8][64]
    float* es = qs + 8 * HD;                 // [8][208]

    const int bh   = blockIdx.x >> 1;
    const int half = blockIdx.x & 1;
    const int b = bh / NH;
    const int h = bh % NH;
    const size_t base = (size_t)b * PERB + (size_t)h * PERH;
    const float* Qg = g_Q + base;
    const float* Kg = g_K + base;
    const float* Vg = g_V + base;
    float* Og = g_AO + base;

    const int tid = threadIdx.x;

    // Load K, V as float4 into padded smem. PERH/4 = 3152 float4s.
    for (int i4 = tid; i4 < PERH / 4; i4 += 256) {
        int r  = i4 >> 4;          // /16 float4 per row
        int c4 = (i4 & 15) * 4;
        float4 kv = *(const float4*)(Kg + i4 * 4);
        float4 vv = *(const float4*)(Vg + i4 * 4);
        *(float4*)(Ks + r * KVS + c4) = kv;
        *(float4*)(Vs + r * KVS + c4) = vv;
    }
    __syncthreads();

    const int w = tid >> 5;
    const int lane = tid & 31;
    float* qrow = qs + w * HD;
    float* erow = es + w * EROW_STRIDE;

    for (int r = w + 8 * half; r < SEQ; r += 16) {
        qrow[lane]      = Qg[r * HD + lane];
        qrow[lane + 32] = Qg[r * HD + lane + 32];
        __syncwarp();

        // energy row: lane handles columns j = lane, lane+32, ...
        float mx = -1e30f;
        for (int j = lane; j < SEQ; j += 32) {
            const float4* kr = (const float4*)(Ks + j * KVS);
            const float4* qv = (const float4*)qrow;
            float e = 0.0f;
            #pragma unroll
            for (int d = 0; d < 16; d++) {
                float4 kq = kr[d];
                float4 qq = qv[d];
                e = fmaf(qq.x, kq.x, e);
                e = fmaf(qq.y, kq.y, e);
                e = fmaf(qq.z, kq.z, e);
                e = fmaf(qq.w, kq.w, e);
            }
            erow[j] = e;
            mx = fmaxf(mx, e);
        }
        #pragma unroll
        for (int o = 16; o > 0; o >>= 1)
            mx = fmaxf(mx, __shfl_xor_sync(0xffffffffu, mx, o));

        float sum = 0.0f;
        for (int j = lane; j < SEQ; j += 32) {
            float p = __expf(erow[j] - mx);
            erow[j] = p;
            sum += p;
        }
        #pragma unroll
        for (int o = 16; o > 0; o >>= 1)
            sum += __shfl_xor_sync(0xffffffffu, sum, o);

        __syncwarp();   // erow[] fully written before all lanes read all j

        // Quirk: softmax first, THEN divide by sqrt(E). Fold into row scale.
        const float inv = 1.0f / (sum * 27.712812921102035f);   // sqrt(768)

        float a0 = 0.0f, a1 = 0.0f;
        #pragma unroll 4
        for (int j = 0; j < SEQ; j++) {
            float p = erow[j];                       // broadcast
            a0 = fmaf(p, Vs[j * KVS + lane],      a0);
            a1 = fmaf(p, Vs[j * KVS + lane + 32], a1);
        }
        Og[r * HD + lane]      = a0 * inv;
        Og[r * HD + lane + 32] = a1 * inv;
        __syncwarp();   // converge before next iteration rewrites qrow/erow
    }
}

// ---------------------------------------------------------------------------
// Launch
// ---------------------------------------------------------------------------
extern "C" void kernel_launch(void* const* d_in, const int* in_sizes, int n_in,
                              void* d_out, int out_size)
{
    const float* x  = (const float*)d_in[0];
    const float* Wq = (const float*)d_in[1];
    const float* bq = (const float*)d_in[2];
    const float* Wk = (const float*)d_in[3];
    const float* bk = (const float*)d_in[4];
    const float* Wv = (const float*)d_in[5];
    const float* bv = (const float*)d_in[6];
    const float* Wp = (const float*)d_in[7];
    const float* bp = (const float*)d_in[8];
    float* out = (float*)d_out;

    // QKV: grid (N/128=6, ceil(M/128)=99, 3 weights)
    dim3 gridQKV(6, 99, 3);
    qkv_gemm_kernel<<<gridQKV, 256>>>(x, Wq, bq, Wk, bk, Wv, bv);

    // Attention: two CTAs per (b,h)
    cudaFuncSetAttribute(attn_kernel,
                         cudaFuncAttributeMaxDynamicSharedMemorySize,
                         ATTN_SMEM_BYTES);
    attn_kernel<<<BATCH * NH * 2, 256, ATTN_SMEM_BYTES>>>();

    // Projection
    dim3 gridP(6, 99, 1);
    proj_gemm_kernel<<<gridP, 256>>>(Wp, bp, out);
}

// round 6
// speedup vs baseline: 1.6397x; 1.6397x over previous
#include <cuda_runtime.h>
#include <cuda_bf16.h>
#include <cstdint>

// Problem constants
#define BATCH 64
#define SEQ   197
#define EDIM  768
#define NH    12
#define HD    64
#define MROWS (BATCH * SEQ)          // 12608
#define PERB  (SEQ * EDIM)
#define PERH  (SEQ * HD)

// fp32 intermediates
__device__ float g_Q[MROWS * EDIM];
__device__ float g_K[MROWS * EDIM];
__device__ float g_V[MROWS * EDIM];
__device__ float g_AO[MROWS * EDIM];

// bf16 split operands (hi + residual lo ~= 16 mantissa bits)
__device__ __align__(16) __nv_bfloat16 g_x_hi[MROWS * EDIM];
__device__ __align__(16) __nv_bfloat16 g_x_lo[MROWS * EDIM];
__device__ __align__(16) __nv_bfloat16 g_w_hi[4][EDIM * EDIM];   // q,k,v,p
__device__ __align__(16) __nv_bfloat16 g_w_lo[4][EDIM * EDIM];
__device__ __align__(16) __nv_bfloat16 g_ao_hi[MROWS * EDIM];
__device__ __align__(16) __nv_bfloat16 g_ao_lo[MROWS * EDIM];

// ---------------------------------------------------------------------------
// bf16 mma.sync helper (supported on plain sm_103 target)
// ---------------------------------------------------------------------------
__device__ __forceinline__ void mma_bf16(
    float& d0, float& d1, float& d2, float& d3,
    unsigned a0, unsigned a1, unsigned a2, unsigned a3,
    unsigned b0, unsigned b1)
{
    asm volatile(
        "mma.sync.aligned.m16n8k16.row.col.f32.bf16.bf16.f32 "
        "{%0,%1,%2,%3}, {%4,%5,%6,%7}, {%8,%9}, {%0,%1,%2,%3};\n"
        : "+f"(d0), "+f"(d1), "+f"(d2), "+f"(d3)
        : "r"(a0), "r"(a1), "r"(a2), "r"(a3), "r"(b0), "r"(b1));
}

// ---------------------------------------------------------------------------
// Split kernel: fp32 -> bf16 hi + bf16 lo (residual)
// sel: 0=x, 1..4=Wq/Wk/Wv/Wp, 5=AO (src ignored, reads g_AO)
// ---------------------------------------------------------------------------
__global__ void split_kernel(const float* __restrict__ src, int sel, int n4)
{
    const float* s = src;
    __nv_bfloat16 *hi, *lo;
    switch (sel) {
        case 0: hi = g_x_hi;    lo = g_x_lo;    break;
        case 1: hi = g_w_hi[0]; lo = g_w_lo[0]; break;
        case 2: hi = g_w_hi[1]; lo = g_w_lo[1]; break;
        case 3: hi = g_w_hi[2]; lo = g_w_lo[2]; break;
        case 4: hi = g_w_hi[3]; lo = g_w_lo[3]; break;
        default: s = g_AO; hi = g_ao_hi; lo = g_ao_lo; break;
    }
    int i = blockIdx.x * blockDim.x + threadIdx.x;
    if (i >= n4) return;
    float4 v = ((const float4*)s)[i];
    __nv_bfloat16 h0 = __float2bfloat16(v.x);
    __nv_bfloat16 h1 = __float2bfloat16(v.y);
    __nv_bfloat16 h2 = __float2bfloat16(v.z);
    __nv_bfloat16 h3 = __float2bfloat16(v.w);
    __nv_bfloat16 l0 = __float2bfloat16(v.x - __bfloat162float(h0));
    __nv_bfloat16 l1 = __float2bfloat16(v.y - __bfloat162float(h1));
    __nv_bfloat16 l2 = __float2bfloat16(v.z - __bfloat162float(h2));
    __nv_bfloat16 l3 = __float2bfloat16(v.w - __bfloat162float(h3));
    uint2 ph, pl;
    ph.x = ((uint32_t)__bfloat16_as_ushort(h1) << 16) | __bfloat16_as_ushort(h0);
    ph.y = ((uint32_t)__bfloat16_as_ushort(h3) << 16) | __bfloat16_as_ushort(h2);
    pl.x = ((uint32_t)__bfloat16_as_ushort(l1) << 16) | __bfloat16_as_ushort(l0);
    pl.y = ((uint32_t)__bfloat16_as_ushort(l3) << 16) | __bfloat16_as_ushort(l2);
    ((uint2*)hi)[i] = ph;
    ((uint2*)lo)[i] = pl;
}

// ---------------------------------------------------------------------------
// bf16-3x NT GEMM: C[M,N] = (Ahi+Alo)[M,K] @ (Bhi+Blo)[N,K]^T + bias
// BM=BN=128, BK=32, 256 threads (warps 2x4, warp tile 64x32 = 4x4 m16n8k16).
// 3 terms: hi*hi + hi*lo + lo*hi. Smem: bf16 pairs as uint, row stride 20
// (bank-conflict-free fragment loads). Single-buffered, reg-prefetched.
// ---------------------------------------------------------------------------
#define RS 20                        // uint stride per row (slots 0..15 used)
#define ST_UINTS (128 * RS)          // 2560 uints = 10240 B per tile
#define GEMM_SMEM_BYTES (4 * ST_UINTS * 4)   // 40960 B

__device__ __forceinline__ uint4 ldg16bf(const __nv_bfloat16* p, bool v) {
    if (v) return *(const uint4*)p;
    return make_uint4(0u, 0u, 0u, 0u);
}

__device__ __forceinline__ void gemm_bf16_body(
    const __nv_bfloat16* __restrict__ Ahi, const __nv_bfloat16* __restrict__ Alo,
    const __nv_bfloat16* __restrict__ Bhi, const __nv_bfloat16* __restrict__ Blo,
    const float* __restrict__ bias, float* __restrict__ C)
{
    extern __shared__ unsigned smem_u[];
    unsigned* As_hi = smem_u;
    unsigned* As_lo = As_hi + ST_UINTS;
    unsigned* Bs_hi = As_lo + ST_UINTS;
    unsigned* Bs_lo = Bs_hi + ST_UINTS;

    const int tid  = threadIdx.x;
    const int warp = tid >> 5;
    const int lane = tid & 31;
    const int g    = lane >> 2;       // 0..7
    const int c    = lane & 3;        // 0..3
    const int warpM = warp & 1;
    const int warpN = warp >> 1;

    const int bm = blockIdx.y * 128;
    const int bn = blockIdx.x * 128;

    // global load assignment: thread -> row tid>>1, k-half (tid&1)*16 bf16
    const int ldRow = tid >> 1;
    const int half  = tid & 1;
    const int aRow  = bm + ldRow;
    const bool aValid = (aRow < MROWS);
    const size_t aOff = (size_t)(aValid ? aRow : 0) * EDIM + half * 16;
    const size_t bOff = (size_t)(bn + ldRow) * EDIM + half * 16;
    const int sBase = ldRow * RS + half * 8;

    float acc[4][4][4];
    #pragma unroll
    for (int mt = 0; mt < 4; mt++)
        #pragma unroll
        for (int nt = 0; nt < 4; nt++)
            #pragma unroll
            for (int r = 0; r < 4; r++)
                acc[mt][nt][r] = 0.0f;

    uint4 rAh[2], rAl[2], rBh[2], rBl[2];
    #pragma unroll
    for (int u = 0; u < 2; u++) {
        rAh[u] = ldg16bf(Ahi + aOff + u * 8, aValid);
        rAl[u] = ldg16bf(Alo + aOff + u * 8, aValid);
        rBh[u] = *(const uint4*)(Bhi + bOff + u * 8);
        rBl[u] = *(const uint4*)(Blo + bOff + u * 8);
    }

    const int nCh = EDIM / 32;   // 24
    for (int ch = 0; ch < nCh; ch++) {
        __syncthreads();
        #pragma unroll
        for (int u = 0; u < 2; u++) {
            *(uint4*)(As_hi + sBase + u * 4) = rAh[u];
            *(uint4*)(As_lo + sBase + u * 4) = rAl[u];
            *(uint4*)(Bs_hi + sBase + u * 4) = rBh[u];
            *(uint4*)(Bs_lo + sBase + u * 4) = rBl[u];
        }
        __syncthreads();

        if (ch + 1 < nCh) {
            const size_t k0 = (size_t)(ch + 1) * 32;
            #pragma unroll
            for (int u = 0; u < 2; u++) {
                rAh[u] = ldg16bf(Ahi + aOff + k0 + u * 8, aValid);
                rAl[u] = ldg16bf(Alo + aOff + k0 + u * 8, aValid);
                rBh[u] = *(const uint4*)(Bhi + bOff + k0 + u * 8);
                rBl[u] = *(const uint4*)(Blo + bOff + k0 + u * 8);
            }
        }

        #pragma unroll
        for (int ks = 0; ks < 2; ks++) {
            const int kk = ks * 8;
            unsigned ah[4][4], al[4][4], bhf[4][2], blf[4][2];
            #pragma unroll
            for (int mt = 0; mt < 4; mt++) {
                const int r0 = (warpM * 64 + mt * 16 + g) * RS + kk;
                const int r1 = r0 + 8 * RS;
                ah[mt][0] = As_hi[r0 + c];
                ah[mt][1] = As_hi[r1 + c];
                ah[mt][2] = As_hi[r0 + c + 4];
                ah[mt][3] = As_hi[r1 + c + 4];
                al[mt][0] = As_lo[r0 + c];
                al[mt][1] = As_lo[r1 + c];
                al[mt][2] = As_lo[r0 + c + 4];
                al[mt][3] = As_lo[r1 + c + 4];
            }
            #pragma unroll
            for (int nt = 0; nt < 4; nt++) {
                const int n0 = (warpN * 32 + nt * 8 + g) * RS + kk;
                bhf[nt][0] = Bs_hi[n0 + c];
                bhf[nt][1] = Bs_hi[n0 + c + 4];
                blf[nt][0] = Bs_lo[n0 + c];
                blf[nt][1] = Bs_lo[n0 + c + 4];
            }
            #pragma unroll
            for (int mt = 0; mt < 4; mt++)
                #pragma unroll
                for (int nt = 0; nt < 4; nt++) {
                    float* d = acc[mt][nt];
                    mma_bf16(d[0], d[1], d[2], d[3],
                             ah[mt][0], ah[mt][1], ah[mt][2], ah[mt][3],
                             bhf[nt][0], bhf[nt][1]);
                    mma_bf16(d[0], d[1], d[2], d[3],
                             ah[mt][0], ah[mt][1], ah[mt][2], ah[mt][3],
                             blf[nt][0], blf[nt][1]);
                    mma_bf16(d[0], d[1], d[2], d[3],
                             al[mt][0], al[mt][1], al[mt][2], al[mt][3],
                             bhf[nt][0], bhf[nt][1]);
                }
        }
    }

    // epilogue
    #pragma unroll
    for (int mt = 0; mt < 4; mt++) {
        const int row0 = bm + warpM * 64 + mt * 16 + g;
        const int row1 = row0 + 8;
        #pragma unroll
        for (int nt = 0; nt < 4; nt++) {
            const int col = bn + warpN * 32 + nt * 8 + 2 * c;
            const float b0 = bias[col];
            const float b1 = bias[col + 1];
            if (row0 < MROWS) {
                float2 v = make_float2(acc[mt][nt][0] + b0, acc[mt][nt][1] + b1);
                *(float2*)(C + (size_t)row0 * EDIM + col) = v;
            }
            if (row1 < MROWS) {
                float2 v = make_float2(acc[mt][nt][2] + b0, acc[mt][nt][3] + b1);
                *(float2*)(C + (size_t)row1 * EDIM + col) = v;
            }
        }
    }
}

__global__ __launch_bounds__(256, 1) void qkv_gemm_kernel(
    const float* __restrict__ bq, const float* __restrict__ bk,
    const float* __restrict__ bv)
{
    const __nv_bfloat16 *wh, *wl;
    const float* bias;
    float* C;
    if (blockIdx.z == 0)      { wh = g_w_hi[0]; wl = g_w_lo[0]; bias = bq; C = g_Q; }
    else if (blockIdx.z == 1) { wh = g_w_hi[1]; wl = g_w_lo[1]; bias = bk; C = g_K; }
    else                      { wh = g_w_hi[2]; wl = g_w_lo[2]; bias = bv; C = g_V; }
    gemm_bf16_body(g_x_hi, g_x_lo, wh, wl, bias, C);
}

__global__ __launch_bounds__(256, 1) void proj_gemm_kernel(
    const float* __restrict__ bp, float* __restrict__ out)
{
    gemm_bf16_body(g_ao_hi, g_ao_lo, g_w_hi[3], g_w_lo[3], bp, out);
}

// ---------------------------------------------------------------------------
// Attention: 2 CTAs per (b,h); each warp processes 4 Q rows jointly.
// K transposed in smem (Kt[64][256], zero-padded cols) -> energy phase is
// FMA-bound: per d, 2x LDS.128 (K) + 4 broadcast (q) feed 32 FMA.
// Softmax quirk: softmax first, then /sqrt(E) (folded into stored p).
// ---------------------------------------------------------------------------
#define KTS 256
#define VS  68
#define ATTN_SMEM_FLOATS (64 * KTS + SEQ * VS + 8 * 4 * 64 + 8 * 4 * 256)
#define ATTN_SMEM_BYTES  (ATTN_SMEM_FLOATS * 4)    // 160080

__device__ __forceinline__ float warp_max(float v) {
    #pragma unroll
    for (int o = 16; o > 0; o >>= 1)
        v = fmaxf(v, __shfl_xor_sync(0xffffffffu, v, o));
    return v;
}
__device__ __forceinline__ float warp_sum(float v) {
    #pragma unroll
    for (int o = 16; o > 0; o >>= 1)
        v += __shfl_xor_sync(0xffffffffu, v, o);
    return v;
}

__global__ __launch_bounds__(256, 1) void attn_kernel()
{
    extern __shared__ float sm[];
    float* Kt = sm;                         // [64][256]  (cols >=197 zero)
    float* Vs = Kt + 64 * KTS;              // [197][68]
    float* qs = Vs + SEQ * VS;              // [8 warps][4 rows][64]
    float* es = qs + 8 * 4 * 64;            // [8 warps][4 rows][256]

    const int bh   = blockIdx.x >> 1;
    const int half = blockIdx.x & 1;
    const int b = bh / NH;
    const int h = bh % NH;
    const size_t base = (size_t)b * PERB + (size_t)h * PERH;
    const float* Qg = g_Q + base;
    const float* Kg = g_K + base;
    const float* Vg = g_V + base;
    float* Og = g_AO + base;

    const int tid = threadIdx.x;

    // zero Kt (covers padding cols/rows)
    for (int i = tid; i < 64 * KTS / 4; i += 256)
        ((float4*)Kt)[i] = make_float4(0.f, 0.f, 0.f, 0.f);
    __syncthreads();

    // transposed K fill: idx -> (d4, j); STS conflict-free (j fastest)
    for (int idx = tid; idx < SEQ * 16; idx += 256) {
        int d4 = idx / SEQ;
        int j  = idx - d4 * SEQ;
        float4 kv = *(const float4*)(Kg + j * HD + d4 * 4);
        Kt[(d4 * 4 + 0) * KTS + j] = kv.x;
        Kt[(d4 * 4 + 1) * KTS + j] = kv.y;
        Kt[(d4 * 4 + 2) * KTS + j] = kv.z;
        Kt[(d4 * 4 + 3) * KTS + j] = kv.w;
    }
    // V row-major, padded stride 68
    for (int i4 = tid; i4 < PERH / 4; i4 += 256) {
        int r  = i4 >> 4;
        int c4 = (i4 & 15) * 4;
        *(float4*)(Vs + r * VS + c4) = *(const float4*)(Vg + i4 * 4);
    }
    __syncthreads();

    const int w = tid >> 5;
    const int lane = tid & 31;
    float* qw = qs + w * 4 * 64;
    float* ew = es + w * 4 * 256;
    const int jA = 4 * lane;          // 0..124
    const int jB = 128 + 4 * lane;    // 128..252 (pad-safe; masked >=SEQ)

    for (int grp = half; grp * 32 < SEQ; grp += 2) {
        const int r0 = grp * 32 + w * 4;

        // stage 4 q rows (zeros if OOB)
        for (int i = lane; i < 256; i += 32) {
            int rr = i >> 6, d = i & 63;
            int gr = r0 + rr;
            qw[i] = (gr < SEQ) ? Qg[gr * HD + d] : 0.f;
        }
        __syncwarp();

        // energy: eA/eB[rr] accumulate 8 j-columns per lane
        float4 eA[4], eB[4];
        #pragma unroll
        for (int rr = 0; rr < 4; rr++) {
            eA[rr] = make_float4(0.f, 0.f, 0.f, 0.f);
            eB[rr] = make_float4(0.f, 0.f, 0.f, 0.f);
        }
        #pragma unroll 2
        for (int d = 0; d < 64; d++) {
            float4 kA = *(const float4*)(Kt + d * KTS + jA);
            float4 kB = *(const float4*)(Kt + d * KTS + jB);
            #pragma unroll
            for (int rr = 0; rr < 4; rr++) {
                float qd = qw[rr * 64 + d];
                eA[rr].x = fmaf(qd, kA.x, eA[rr].x);
                eA[rr].y = fmaf(qd, kA.y, eA[rr].y);
                eA[rr].z = fmaf(qd, kA.z, eA[rr].z);
                eA[rr].w = fmaf(qd, kA.w, eA[rr].w);
                eB[rr].x = fmaf(qd, kB.x, eB[rr].x);
                eB[rr].y = fmaf(qd, kB.y, eB[rr].y);
                eB[rr].z = fmaf(qd, kB.z, eB[rr].z);
                eB[rr].w = fmaf(qd, kB.w, eB[rr].w);
            }
        }

        // per-row softmax; fold 1/(sum*sqrt(768)) into stored p
        #pragma unroll
        for (int rr = 0; rr < 4; rr++) {
            float4 ea = eA[rr], eb = eB[rr];
            if (jB + 0 >= SEQ) eb.x = -1e30f;
            if (jB + 1 >= SEQ) eb.y = -1e30f;
            if (jB + 2 >= SEQ) eb.z = -1e30f;
            if (jB + 3 >= SEQ) eb.w = -1e30f;
            float m = fmaxf(fmaxf(fmaxf(ea.x, ea.y), fmaxf(ea.z, ea.w)),
                            fmaxf(fmaxf(eb.x, eb.y), fmaxf(eb.z, eb.w)));
            m = warp_max(m);
            float4 pa, pb;
            pa.x = __expf(ea.x - m); pa.y = __expf(ea.y - m);
            pa.z = __expf(ea.z - m); pa.w = __expf(ea.w - m);
            pb.x = __expf(eb.x - m); pb.y = __expf(eb.y - m);
            pb.z = __expf(eb.z - m); pb.w = __expf(eb.w - m);
            float s = pa.x + pa.y + pa.z + pa.w + pb.x + pb.y + pb.z + pb.w;
            s = warp_sum(s);
            float inv = 1.0f / (s * 27.712812921102035f);   // sqrt(768)
            pa.x *= inv; pa.y *= inv; pa.z *= inv; pa.w *= inv;
            pb.x *= inv; pb.y *= inv; pb.z *= inv; pb.w *= inv;
            *(float4*)(ew + rr * 256 + jA) = pa;
            *(float4*)(ew + rr * 256 + jB) = pb;
        }
        __syncwarp();

        // PV: lanes own output dims (lane, lane+32); 4 rows share V loads
        float a0[4], a1[4];
        #pragma unroll
        for (int rr = 0; rr < 4; rr++) { a0[rr] = 0.f; a1[rr] = 0.f; }
        #pragma unroll 2
        for (int j = 0; j < SEQ; j++) {
            float v0 = Vs[j * VS + lane];
            float v1 = Vs[j * VS + lane + 32];
            #pragma unroll
            for (int rr = 0; rr < 4; rr++) {
                float p = ew[rr * 256 + j];
                a0[rr] = fmaf(p, v0, a0[rr]);
                a1[rr] = fmaf(p, v1, a1[rr]);
            }
        }
        #pragma unroll
        for (int rr = 0; rr < 4; rr++) {
            int gr = r0 + rr;
            if (gr < SEQ) {
                Og[gr * HD + lane]      = a0[rr];
                Og[gr * HD + lane + 32] = a1[rr];
            }
        }
        __syncwarp();
    }
}

// ---------------------------------------------------------------------------
// Launch
// ---------------------------------------------------------------------------
extern "C" void kernel_launch(void* const* d_in, const int* in_sizes, int n_in,
                              void* d_out, int out_size)
{
    const float* x  = (const float*)d_in[0];
    const float* Wq = (const float*)d_in[1];
    const float* bq = (const float*)d_in[2];
    const float* Wk = (const float*)d_in[3];
    const float* bk = (const float*)d_in[4];
    const float* Wv = (const float*)d_in[5];
    const float* bv = (const float*)d_in[6];
    const float* Wp = (const float*)d_in[7];
    const float* bp = (const float*)d_in[8];
    float* out = (float*)d_out;

    cudaFuncSetAttribute(attn_kernel,
                         cudaFuncAttributeMaxDynamicSharedMemorySize,
                         ATTN_SMEM_BYTES);

    const int n4x = MROWS * EDIM / 4;
    const int n4w = EDIM * EDIM / 4;
    split_kernel<<<(n4x + 255) / 256, 256>>>(x, 0, n4x);
    split_kernel<<<(n4w + 255) / 256, 256>>>(Wq, 1, n4w);
    split_kernel<<<(n4w + 255) / 256, 256>>>(Wk, 2, n4w);
    split_kernel<<<(n4w + 255) / 256, 256>>>(Wv, 3, n4w);
    split_kernel<<<(n4w + 255) / 256, 256>>>(Wp, 4, n4w);

    dim3 gridQKV(EDIM / 128, (MROWS + 127) / 128, 3);   // (6, 99, 3)
    qkv_gemm_kernel<<<gridQKV, 256, GEMM_SMEM_BYTES>>>(bq, bk, bv);

    attn_kernel<<<BATCH * NH * 2, 256, ATTN_SMEM_BYTES>>>();

    split_kernel<<<(n4x + 255) / 256, 256>>>(nullptr, 5, n4x);
    dim3 gridP(EDIM / 128, (MROWS + 127) / 128, 1);     // (6, 99)
    proj_gemm_kernel<<<gridP, 256, GEMM_SMEM_BYTES>>>(bp, out);
}

// round 7
// speedup vs baseline: 2.1582x; 1.3162x over previous
#include <cuda_runtime.h>
#include <cuda_bf16.h>
#include <cstdint>

// Problem constants
#define BATCH 64
#define SEQ   197
#define EDIM  768
#define NH    12
#define HD    64
#define MROWS (BATCH * SEQ)          // 12608
#define PERB  (SEQ * EDIM)
#define PERH  (SEQ * HD)

// bf16 split operands (hi + residual lo ~= 16 mantissa bits)
__device__ __align__(16) __nv_bfloat16 g_x_hi[MROWS * EDIM];
__device__ __align__(16) __nv_bfloat16 g_x_lo[MROWS * EDIM];
__device__ __align__(16) __nv_bfloat16 g_w_hi[4][EDIM * EDIM];   // q,k,v,p
__device__ __align__(16) __nv_bfloat16 g_w_lo[4][EDIM * EDIM];
__device__ __align__(16) __nv_bfloat16 g_q_hi[MROWS * EDIM / 12 * 12];
// Q/K/V per-head layout identical to fp32 versions: [MROWS*EDIM] elements
__device__ __align__(16) __nv_bfloat16 g_q_lo[MROWS * EDIM];
__device__ __align__(16) __nv_bfloat16 g_k_hi[MROWS * EDIM];
__device__ __align__(16) __nv_bfloat16 g_k_lo[MROWS * EDIM];
__device__ __align__(16) __nv_bfloat16 g_v_hi[MROWS * EDIM];
__device__ __align__(16) __nv_bfloat16 g_v_lo[MROWS * EDIM];
__device__ __align__(16) __nv_bfloat16 g_ao_hi[MROWS * EDIM];
__device__ __align__(16) __nv_bfloat16 g_ao_lo[MROWS * EDIM];

// ---------------------------------------------------------------------------
// bf16 mma.sync helper
// ---------------------------------------------------------------------------
__device__ __forceinline__ void mma_bf16(
    float& d0, float& d1, float& d2, float& d3,
    unsigned a0, unsigned a1, unsigned a2, unsigned a3,
    unsigned b0, unsigned b1)
{
    asm volatile(
        "mma.sync.aligned.m16n8k16.row.col.f32.bf16.bf16.f32 "
        "{%0,%1,%2,%3}, {%4,%5,%6,%7}, {%8,%9}, {%0,%1,%2,%3};\n"
        : "+f"(d0), "+f"(d1), "+f"(d2), "+f"(d3)
        : "r"(a0), "r"(a1), "r"(a2), "r"(a3), "r"(b0), "r"(b1));
}

__device__ __forceinline__ unsigned prmt(unsigned a, unsigned b, unsigned sel) {
    unsigned r;
    asm("prmt.b32 %0, %1, %2, %3;" : "=r"(r) : "r"(a), "r"(b), "r"(sel));
    return r;
}

__device__ __forceinline__ unsigned pack_hi2(float v0, float v1) {
    __nv_bfloat162 h = __floats2bfloat162_rn(v0, v1);
    return *reinterpret_cast<unsigned*>(&h);
}

// ---------------------------------------------------------------------------
// Split kernel: fp32 -> bf16 hi + bf16 lo (residual). sel 0=x, 1..4=W
// ---------------------------------------------------------------------------
__global__ void split_kernel(const float* __restrict__ src, int sel, int n4)
{
    __nv_bfloat16 *hi, *lo;
    switch (sel) {
        case 0: hi = g_x_hi;    lo = g_x_lo;    break;
        case 1: hi = g_w_hi[0]; lo = g_w_lo[0]; break;
        case 2: hi = g_w_hi[1]; lo = g_w_lo[1]; break;
        case 3: hi = g_w_hi[2]; lo = g_w_lo[2]; break;
        default: hi = g_w_hi[3]; lo = g_w_lo[3]; break;
    }
    int i = blockIdx.x * blockDim.x + threadIdx.x;
    if (i >= n4) return;
    float4 v = ((const float4*)src)[i];
    __nv_bfloat16 h0 = __float2bfloat16(v.x);
    __nv_bfloat16 h1 = __float2bfloat16(v.y);
    __nv_bfloat16 h2 = __float2bfloat16(v.z);
    __nv_bfloat16 h3 = __float2bfloat16(v.w);
    __nv_bfloat16 l0 = __float2bfloat16(v.x - __bfloat162float(h0));
    __nv_bfloat16 l1 = __float2bfloat16(v.y - __bfloat162float(h1));
    __nv_bfloat16 l2 = __float2bfloat16(v.z - __bfloat162float(h2));
    __nv_bfloat16 l3 = __float2bfloat16(v.w - __bfloat162float(h3));
    uint2 ph, pl;
    ph.x = ((uint32_t)__bfloat16_as_ushort(h1) << 16) | __bfloat16_as_ushort(h0);
    ph.y = ((uint32_t)__bfloat16_as_ushort(h3) << 16) | __bfloat16_as_ushort(h2);
    pl.x = ((uint32_t)__bfloat16_as_ushort(l1) << 16) | __bfloat16_as_ushort(l0);
    pl.y = ((uint32_t)__bfloat16_as_ushort(l3) << 16) | __bfloat16_as_ushort(l2);
    ((uint2*)hi)[i] = ph;
    ((uint2*)lo)[i] = pl;
}

// ---------------------------------------------------------------------------
// bf16-3x NT GEMM (as R6): BM=BN=128, BK=32, warp tile 64x32.
// OutMode 0: fp32 C + bias.  OutMode 1: bf16 hi/lo split outputs + bias.
// ---------------------------------------------------------------------------
#define RS 20
#define ST_UINTS (128 * RS)
#define GEMM_SMEM_BYTES (4 * ST_UINTS * 4)

__device__ __forceinline__ uint4 ldg16bf(const __nv_bfloat16* p, bool v) {
    if (v) return *(const uint4*)p;
    return make_uint4(0u, 0u, 0u, 0u);
}

template <int OUT_SPLIT>
__device__ __forceinline__ void gemm_bf16_body(
    const __nv_bfloat16* __restrict__ Ahi, const __nv_bfloat16* __restrict__ Alo,
    const __nv_bfloat16* __restrict__ Bhi, const __nv_bfloat16* __restrict__ Blo,
    const float* __restrict__ bias,
    float* __restrict__ C,
    __nv_bfloat16* __restrict__ Chi, __nv_bfloat16* __restrict__ Clo)
{
    extern __shared__ unsigned smem_u[];
    unsigned* As_hi = smem_u;
    unsigned* As_lo = As_hi + ST_UINTS;
    unsigned* Bs_hi = As_lo + ST_UINTS;
    unsigned* Bs_lo = Bs_hi + ST_UINTS;

    const int tid  = threadIdx.x;
    const int warp = tid >> 5;
    const int lane = tid & 31;
    const int g    = lane >> 2;
    const int c    = lane & 3;
    const int warpM = warp & 1;
    const int warpN = warp >> 1;

    const int bm = blockIdx.y * 128;
    const int bn = blockIdx.x * 128;

    const int ldRow = tid >> 1;
    const int half  = tid & 1;
    const int aRow  = bm + ldRow;
    const bool aValid = (aRow < MROWS);
    const size_t aOff = (size_t)(aValid ? aRow : 0) * EDIM + half * 16;
    const size_t bOff = (size_t)(bn + ldRow) * EDIM + half * 16;
    const int sBase = ldRow * RS + half * 8;

    float acc[4][4][4];
    #pragma unroll
    for (int mt = 0; mt < 4; mt++)
        #pragma unroll
        for (int nt = 0; nt < 4; nt++)
            #pragma unroll
            for (int r = 0; r < 4; r++)
                acc[mt][nt][r] = 0.0f;

    uint4 rAh[2], rAl[2], rBh[2], rBl[2];
    #pragma unroll
    for (int u = 0; u < 2; u++) {
        rAh[u] = ldg16bf(Ahi + aOff + u * 8, aValid);
        rAl[u] = ldg16bf(Alo + aOff + u * 8, aValid);
        rBh[u] = *(const uint4*)(Bhi + bOff + u * 8);
        rBl[u] = *(const uint4*)(Blo + bOff + u * 8);
    }

    const int nCh = EDIM / 32;
    for (int ch = 0; ch < nCh; ch++) {
        __syncthreads();
        #pragma unroll
        for (int u = 0; u < 2; u++) {
            *(uint4*)(As_hi + sBase + u * 4) = rAh[u];
            *(uint4*)(As_lo + sBase + u * 4) = rAl[u];
            *(uint4*)(Bs_hi + sBase + u * 4) = rBh[u];
            *(uint4*)(Bs_lo + sBase + u * 4) = rBl[u];
        }
        __syncthreads();

        if (ch + 1 < nCh) {
            const size_t k0 = (size_t)(ch + 1) * 32;
            #pragma unroll
            for (int u = 0; u < 2; u++) {
                rAh[u] = ldg16bf(Ahi + aOff + k0 + u * 8, aValid);
                rAl[u] = ldg16bf(Alo + aOff + k0 + u * 8, aValid);
                rBh[u] = *(const uint4*)(Bhi + bOff + k0 + u * 8);
                rBl[u] = *(const uint4*)(Blo + bOff + k0 + u * 8);
            }
        }

        #pragma unroll
        for (int ks = 0; ks < 2; ks++) {
            const int kk = ks * 8;
            unsigned ah[4][4], al[4][4], bhf[4][2], blf[4][2];
            #pragma unroll
            for (int mt = 0; mt < 4; mt++) {
                const int r0 = (warpM * 64 + mt * 16 + g) * RS + kk;
                const int r1 = r0 + 8 * RS;
                ah[mt][0] = As_hi[r0 + c];
                ah[mt][1] = As_hi[r1 + c];
                ah[mt][2] = As_hi[r0 + c + 4];
                ah[mt][3] = As_hi[r1 + c + 4];
                al[mt][0] = As_lo[r0 + c];
                al[mt][1] = As_lo[r1 + c];
                al[mt][2] = As_lo[r0 + c + 4];
                al[mt][3] = As_lo[r1 + c + 4];
            }
            #pragma unroll
            for (int nt = 0; nt < 4; nt++) {
                const int n0 = (warpN * 32 + nt * 8 + g) * RS + kk;
                bhf[nt][0] = Bs_hi[n0 + c];
                bhf[nt][1] = Bs_hi[n0 + c + 4];
                blf[nt][0] = Bs_lo[n0 + c];
                blf[nt][1] = Bs_lo[n0 + c + 4];
            }
            #pragma unroll
            for (int mt = 0; mt < 4; mt++)
                #pragma unroll
                for (int nt = 0; nt < 4; nt++) {
                    float* d = acc[mt][nt];
                    mma_bf16(d[0], d[1], d[2], d[3],
                             ah[mt][0], ah[mt][1], ah[mt][2], ah[mt][3],
                             bhf[nt][0], bhf[nt][1]);
                    mma_bf16(d[0], d[1], d[2], d[3],
                             ah[mt][0], ah[mt][1], ah[mt][2], ah[mt][3],
                             blf[nt][0], blf[nt][1]);
                    mma_bf16(d[0], d[1], d[2], d[3],
                             al[mt][0], al[mt][1], al[mt][2], al[mt][3],
                             bhf[nt][0], bhf[nt][1]);
                }
        }
    }

    // epilogue
    #pragma unroll
    for (int mt = 0; mt < 4; mt++) {
        const int row0 = bm + warpM * 64 + mt * 16 + g;
        const int row1 = row0 + 8;
        #pragma unroll
        for (int nt = 0; nt < 4; nt++) {
            const int col = bn + warpN * 32 + nt * 8 + 2 * c;
            const float b0 = bias[col];
            const float b1 = bias[col + 1];
            float v00 = acc[mt][nt][0] + b0, v01 = acc[mt][nt][1] + b1;
            float v10 = acc[mt][nt][2] + b0, v11 = acc[mt][nt][3] + b1;
            if (OUT_SPLIT) {
                if (row0 < MROWS) {
                    size_t ui = ((size_t)row0 * EDIM + col) >> 1;
                    float h0 = __bfloat162float(__float2bfloat16(v00));
                    float h1 = __bfloat162float(__float2bfloat16(v01));
                    ((unsigned*)Chi)[ui] = pack_hi2(v00, v01);
                    ((unsigned*)Clo)[ui] = pack_hi2(v00 - h0, v01 - h1);
                }
                if (row1 < MROWS) {
                    size_t ui = ((size_t)row1 * EDIM + col) >> 1;
                    float h0 = __bfloat162float(__float2bfloat16(v10));
                    float h1 = __bfloat162float(__float2bfloat16(v11));
                    ((unsigned*)Chi)[ui] = pack_hi2(v10, v11);
                    ((unsigned*)Clo)[ui] = pack_hi2(v10 - h0, v11 - h1);
                }
            } else {
                if (row0 < MROWS)
                    *(float2*)(C + (size_t)row0 * EDIM + col) = make_float2(v00, v01);
                if (row1 < MROWS)
                    *(float2*)(C + (size_t)row1 * EDIM + col) = make_float2(v10, v11);
            }
        }
    }
}

__global__ __launch_bounds__(256, 1) void qkv_gemm_kernel(
    const float* __restrict__ bq, const float* __restrict__ bk,
    const float* __restrict__ bv)
{
    const __nv_bfloat16 *wh, *wl;
    const float* bias;
    __nv_bfloat16 *ch, *cl;
    if (blockIdx.z == 0)      { wh = g_w_hi[0]; wl = g_w_lo[0]; bias = bq; ch = g_q_hi; cl = g_q_lo; }
    else if (blockIdx.z == 1) { wh = g_w_hi[1]; wl = g_w_lo[1]; bias = bk; ch = g_k_hi; cl = g_k_lo; }
    else                      { wh = g_w_hi[2]; wl = g_w_lo[2]; bias = bv; ch = g_v_hi; cl = g_v_lo; }
    gemm_bf16_body<1>(g_x_hi, g_x_lo, wh, wl, bias, nullptr, ch, cl);
}

__global__ __launch_bounds__(256, 1) void proj_gemm_kernel(
    const float* __restrict__ bp, float* __restrict__ out)
{
    gemm_bf16_body<0>(g_ao_hi, g_ao_lo, g_w_hi[3], g_w_lo[3], bp, out, nullptr, nullptr);
}

// ---------------------------------------------------------------------------
// Attention via mma.sync bf16-3x. One CTA per (b,h), 256 threads.
// K hi/lo [224 rows x 64] (uint stride 36), Vt hi/lo [64 x 224] (stride 116),
// E fp32 [32 x 232], P hi/lo uints [32 x 116]. 7 stripes of 32 Q rows.
// Softmax quirk: softmax first, then /sqrt(E) (folded into P).
// ---------------------------------------------------------------------------
#define SP   224
#define KSU  36          // uint stride for Q/K rows (32 used + 4 pad)
#define VSU  116         // uint stride for Vt / P rows (112 used + 4 pad)
#define ES   232         // float stride for E rows

#define SM_KH   0
#define SM_KL   (SM_KH + SP * KSU)               //  8064
#define SM_VTH  (SM_KL + SP * KSU)               // 16128
#define SM_VTL  (SM_VTH + 64 * VSU)              // 23552
#define SM_QH   (SM_VTL + 64 * VSU)              // 30976
#define SM_QL   (SM_QH + 32 * KSU)               // 32128
#define SM_E    (SM_QL + 32 * KSU)               // 33280
#define SM_PH   (SM_E + 32 * ES)                 // 40704
#define SM_PL   (SM_PH + 32 * VSU)               // 44416
#define ATTN_SMEM_WORDS (SM_PL + 32 * VSU)       // 48128
#define ATTN_SMEM_BYTES (ATTN_SMEM_WORDS * 4)    // 192512

__global__ __launch_bounds__(256, 1) void attn_kernel()
{
    extern __shared__ unsigned smw[];
    unsigned* Kh  = smw + SM_KH;
    unsigned* Kl  = smw + SM_KL;
    unsigned* Vth = smw + SM_VTH;
    unsigned* Vtl = smw + SM_VTL;
    unsigned* Qh  = smw + SM_QH;
    unsigned* Ql  = smw + SM_QL;
    float*    E   = (float*)(smw + SM_E);
    unsigned* Ph  = smw + SM_PH;
    unsigned* Pl  = smw + SM_PL;

    const int bh = blockIdx.x;
    const int b = bh / NH;
    const int h = bh % NH;
    const size_t base = (size_t)b * PERB + (size_t)h * PERH;   // even

    const unsigned* Qgh = (const unsigned*)g_q_hi + (base >> 1);
    const unsigned* Qgl = (const unsigned*)g_q_lo + (base >> 1);
    const unsigned* Kgh = (const unsigned*)g_k_hi + (base >> 1);
    const unsigned* Kgl = (const unsigned*)g_k_lo + (base >> 1);
    const unsigned* Vgh = (const unsigned*)g_v_hi + (base >> 1);
    const unsigned* Vgl = (const unsigned*)g_v_lo + (base >> 1);
    unsigned* AOh = (unsigned*)g_ao_hi + (base >> 1);
    unsigned* AOl = (unsigned*)g_ao_lo + (base >> 1);

    const int tid  = threadIdx.x;
    const int warp = tid >> 5;
    const int lane = tid & 31;
    const int g    = lane >> 2;
    const int c    = lane & 3;
    const int wM   = warp & 1;      // 0..1 (M 16-row tile within stripe)
    const int wN   = warp >> 1;     // 0..3

    // zero K/V smem region (covers pad rows/cols)
    for (int i = tid; i < (SP * KSU * 2 + 64 * VSU * 2) / 4; i += 256)
        ((uint4*)smw)[i] = make_uint4(0u, 0u, 0u, 0u);
    __syncthreads();

    // K fill: 197 rows x 8 uint4 chunks (row = 32 uints of bf16)
    for (int t = tid; t < 197 * 8; t += 256) {
        int row = t >> 3, chk = t & 7;
        uint4 vh = *(const uint4*)(Kgh + row * 32 + chk * 4);
        uint4 vl = *(const uint4*)(Kgl + row * 32 + chk * 4);
        *(uint4*)(Kh + row * KSU + chk * 4) = vh;
        *(uint4*)(Kl + row * KSU + chk * 4) = vl;
    }
    // Vt fill (transpose + repack along j): 99 j-pairs x 8 d-chunks
    for (int t = tid; t < 99 * 8; t += 256) {
        int j2 = t >> 3, dch = t & 7;
        int j0 = 2 * j2;
        uint4 ah = *(const uint4*)(Vgh + j0 * 32 + dch * 4);
        uint4 al = *(const uint4*)(Vgl + j0 * 32 + dch * 4);
        uint4 bhv = make_uint4(0u, 0u, 0u, 0u), blv = bhv;
        if (j0 + 1 < SEQ) {
            bhv = *(const uint4*)(Vgh + (j0 + 1) * 32 + dch * 4);
            blv = *(const uint4*)(Vgl + (j0 + 1) * 32 + dch * 4);
        }
        const unsigned* av[2] = {&ah.x, &al.x};
        const unsigned* bv[2] = {&bhv.x, &blv.x};
        unsigned* dst[2] = {Vth, Vtl};
        #pragma unroll
        for (int s = 0; s < 2; s++) {
            #pragma unroll
            for (int i = 0; i < 4; i++) {
                int d = dch * 8 + 2 * i;
                dst[s][(d    ) * VSU + j2] = prmt(av[s][i], bv[s][i], 0x5410);
                dst[s][(d + 1) * VSU + j2] = prmt(av[s][i], bv[s][i], 0x7632);
            }
        }
    }
    __syncthreads();

    for (int stripe = 0; stripe < 7; stripe++) {
        const int rbase = stripe * 32;

        // ---- load Q stripe (32 rows x 8 uint4) ----
        {
            int row = tid >> 3, chk = tid & 7;
            int rg = rbase + row;
            uint4 vh = make_uint4(0u, 0u, 0u, 0u), vl = vh;
            if (rg < SEQ) {
                vh = *(const uint4*)(Qgh + rg * 32 + chk * 4);
                vl = *(const uint4*)(Qgl + rg * 32 + chk * 4);
            }
            *(uint4*)(Qh + row * KSU + chk * 4) = vh;
            *(uint4*)(Ql + row * KSU + chk * 4) = vl;
        }
        __syncthreads();

        // ---- E = Q_stripe @ K^T  (warp: m16 x 7 n8-tiles) ----
        {
            float e[7][4];
            #pragma unroll
            for (int t = 0; t < 7; t++)
                #pragma unroll
                for (int r = 0; r < 4; r++) e[t][r] = 0.f;

            #pragma unroll
            for (int ks = 0; ks < 4; ks++) {
                const int kk = ks * 8;
                const int r0 = (wM * 16 + g) * KSU + kk;
                const int r1 = r0 + 8 * KSU;
                unsigned ah0 = Qh[r0 + c], ah1 = Qh[r1 + c];
                unsigned ah2 = Qh[r0 + c + 4], ah3 = Qh[r1 + c + 4];
                unsigned al0 = Ql[r0 + c], al1 = Ql[r1 + c];
                unsigned al2 = Ql[r0 + c + 4], al3 = Ql[r1 + c + 4];
                #pragma unroll
                for (int t = 0; t < 7; t++) {
                    const int n0 = (wN * 56 + t * 8 + g) * KSU + kk;
                    unsigned bh0 = Kh[n0 + c], bh1 = Kh[n0 + c + 4];
                    unsigned bl0 = Kl[n0 + c], bl1 = Kl[n0 + c + 4];
                    mma_bf16(e[t][0], e[t][1], e[t][2], e[t][3],
                             ah0, ah1, ah2, ah3, bh0, bh1);
                    mma_bf16(e[t][0], e[t][1], e[t][2], e[t][3],
                             ah0, ah1, ah2, ah3, bl0, bl1);
                    mma_bf16(e[t][0], e[t][1], e[t][2], e[t][3],
                             al0, al1, al2, al3, bh0, bh1);
                }
            }
            // store E to smem
            #pragma unroll
            for (int t = 0; t < 7; t++) {
                const int col = wN * 56 + t * 8 + 2 * c;
                const int row = wM * 16 + g;
                *(float2*)(E + row * ES + col)       = make_float2(e[t][0], e[t][1]);
                *(float2*)(E + (row + 8) * ES + col) = make_float2(e[t][2], e[t][3]);
            }
        }
        __syncthreads();

        // ---- softmax rows (warp w owns rows 4w..4w+3), write P hi/lo ----
        {
            #pragma unroll
            for (int rr = 0; rr < 4; rr++) {
                const int row = warp * 4 + rr;
                const float* er = E + row * ES;
                float e0[4], e1[4];
                float mx = -1e30f;
                int cnt = 0;
                for (int p2 = lane; p2 < 112; p2 += 32, cnt++) {
                    float2 ev = *(const float2*)(er + 2 * p2);
                    e0[cnt] = (2 * p2     < SEQ) ? ev.x : -1e30f;
                    e1[cnt] = (2 * p2 + 1 < SEQ) ? ev.y : -1e30f;
                    mx = fmaxf(mx, fmaxf(e0[cnt], e1[cnt]));
                }
                #pragma unroll
                for (int o = 16; o > 0; o >>= 1)
                    mx = fmaxf(mx, __shfl_xor_sync(0xffffffffu, mx, o));
                float sum = 0.f;
                #pragma unroll
                for (int i = 0; i < 4; i++) {
                    if (i < cnt) {
                        e0[i] = __expf(e0[i] - mx);
                        e1[i] = __expf(e1[i] - mx);
                        sum += e0[i] + e1[i];
                    }
                }
                #pragma unroll
                for (int o = 16; o > 0; o >>= 1)
                    sum += __shfl_xor_sync(0xffffffffu, sum, o);
                const float inv = 1.0f / (sum * 27.712812921102035f);  // sqrt(768)
                cnt = 0;
                for (int p2 = lane; p2 < 112; p2 += 32, cnt++) {
                    float p0 = e0[cnt] * inv;
                    float p1 = e1[cnt] * inv;
                    float h0 = __bfloat162float(__float2bfloat16(p0));
                    float h1 = __bfloat162float(__float2bfloat16(p1));
                    Ph[row * VSU + p2] = pack_hi2(p0, p1);
                    Pl[row * VSU + p2] = pack_hi2(p0 - h0, p1 - h1);
                }
            }
        }
        __syncthreads();

        // ---- O_stripe = P @ V  (warp: m16 x 2 n8-tiles over 64 d) ----
        {
            float o[2][4];
            #pragma unroll
            for (int t = 0; t < 2; t++)
                #pragma unroll
                for (int r = 0; r < 4; r++) o[t][r] = 0.f;

            #pragma unroll 2
            for (int ks = 0; ks < 14; ks++) {
                const int kk = ks * 8;
                const int r0 = (wM * 16 + g) * VSU + kk;
                const int r1 = r0 + 8 * VSU;
                unsigned ah0 = Ph[r0 + c], ah1 = Ph[r1 + c];
                unsigned ah2 = Ph[r0 + c + 4], ah3 = Ph[r1 + c + 4];
                unsigned al0 = Pl[r0 + c], al1 = Pl[r1 + c];
                unsigned al2 = Pl[r0 + c + 4], al3 = Pl[r1 + c + 4];
                #pragma unroll
                for (int t = 0; t < 2; t++) {
                    const int n0 = (wN * 16 + t * 8 + g) * VSU + kk;
                    unsigned bh0 = Vth[n0 + c], bh1 = Vth[n0 + c + 4];
                    unsigned bl0 = Vtl[n0 + c], bl1 = Vtl[n0 + c + 4];
                    mma_bf16(o[t][0], o[t][1], o[t][2], o[t][3],
                             ah0, ah1, ah2, ah3, bh0, bh1);
                    mma_bf16(o[t][0], o[t][1], o[t][2], o[t][3],
                             ah0, ah1, ah2, ah3, bl0, bl1);
                    mma_bf16(o[t][0], o[t][1], o[t][2], o[t][3],
                             al0, al1, al2, al3, bh0, bh1);
                }
            }
            // write O rows -> AO hi/lo
            #pragma unroll
            for (int t = 0; t < 2; t++) {
                const int col = wN * 16 + t * 8 + 2 * c;
                const int rg0 = rbase + wM * 16 + g;
                const int rg1 = rg0 + 8;
                if (rg0 < SEQ) {
                    float h0 = __bfloat162float(__float2bfloat16(o[t][0]));
                    float h1 = __bfloat162float(__float2bfloat16(o[t][1]));
                    AOh[(rg0 * HD + col) >> 1] = pack_hi2(o[t][0], o[t][1]);
                    AOl[(rg0 * HD + col) >> 1] = pack_hi2(o[t][0] - h0, o[t][1] - h1);
                }
                if (rg1 < SEQ) {
                    float h0 = __bfloat162float(__float2bfloat16(o[t][2]));
                    float h1 = __bfloat162float(__float2bfloat16(o[t][3]));
                    AOh[(rg1 * HD + col) >> 1] = pack_hi2(o[t][2], o[t][3]);
                    AOl[(rg1 * HD + col) >> 1] = pack_hi2(o[t][2] - h0, o[t][3] - h1);
                }
            }
        }
        __syncthreads();
    }
}

// ---------------------------------------------------------------------------
// Launch
// ---------------------------------------------------------------------------
extern "C" void kernel_launch(void* const* d_in, const int* in_sizes, int n_in,
                              void* d_out, int out_size)
{
    const float* x  = (const float*)d_in[0];
    const float* Wq = (const float*)d_in[1];
    const float* bq = (const float*)d_in[2];
    const float* Wk = (const float*)d_in[3];
    const float* bk = (const float*)d_in[4];
    const float* Wv = (const float*)d_in[5];
    const float* bv = (const float*)d_in[6];
    const float* Wp = (const float*)d_in[7];
    const float* bp = (const float*)d_in[8];
    float* out = (float*)d_out;

    cudaFuncSetAttribute(attn_kernel,
                         cudaFuncAttributeMaxDynamicSharedMemorySize,
                         ATTN_SMEM_BYTES);

    const int n4x = MROWS * EDIM / 4;
    const int n4w = EDIM * EDIM / 4;
    split_kernel<<<(n4x + 255) / 256, 256>>>(x, 0, n4x);
    split_kernel<<<(n4w + 255) / 256, 256>>>(Wq, 1, n4w);
    split_kernel<<<(n4w + 255) / 256, 256>>>(Wk, 2, n4w);
    split_kernel<<<(n4w + 255) / 256, 256>>>(Wv, 3, n4w);
    split_kernel<<<(n4w + 255) / 256, 256>>>(Wp, 4, n4w);

    dim3 gridQKV(EDIM / 128, (MROWS + 127) / 128, 3);   // (6, 99, 3)
    qkv_gemm_kernel<<<gridQKV, 256, GEMM_SMEM_BYTES>>>(bq, bk, bv);

    attn_kernel<<<BATCH * NH, 256, ATTN_SMEM_BYTES>>>();

    dim3 gridP(EDIM / 128, (MROWS + 127) / 128, 1);     // (6, 99)
    proj_gemm_kernel<<<gridP, 256, GEMM_SMEM_BYTES>>>(bp, out);
}

// round 8
// speedup vs baseline: 2.5816x; 1.1962x over previous
#include <cuda_runtime.h>
#include <cuda_bf16.h>
#include <cstdint>

// Problem constants
#define BATCH 64
#define SEQ   197
#define EDIM  768
#define NH    12
#define HD    64
#define MROWS (BATCH * SEQ)          // 12608
#define PERB  (SEQ * EDIM)
#define PERH  (SEQ * HD)

// bf16 split operands (hi + residual lo ~= 16 mantissa bits)
__device__ __align__(16) __nv_bfloat16 g_x_hi[MROWS * EDIM];
__device__ __align__(16) __nv_bfloat16 g_x_lo[MROWS * EDIM];
__device__ __align__(16) __nv_bfloat16 g_w_hi[4][EDIM * EDIM];   // q,k,v,p
__device__ __align__(16) __nv_bfloat16 g_w_lo[4][EDIM * EDIM];
__device__ __align__(16) __nv_bfloat16 g_q_hi[MROWS * EDIM];
__device__ __align__(16) __nv_bfloat16 g_q_lo[MROWS * EDIM];
__device__ __align__(16) __nv_bfloat16 g_k_hi[MROWS * EDIM];
__device__ __align__(16) __nv_bfloat16 g_k_lo[MROWS * EDIM];
__device__ __align__(16) __nv_bfloat16 g_v_hi[MROWS * EDIM];
__device__ __align__(16) __nv_bfloat16 g_v_lo[MROWS * EDIM];
__device__ __align__(16) __nv_bfloat16 g_ao_hi[MROWS * EDIM];
__device__ __align__(16) __nv_bfloat16 g_ao_lo[MROWS * EDIM];

// ---------------------------------------------------------------------------
// mma / ldmatrix helpers (all legal on plain compute_103 target)
// ---------------------------------------------------------------------------
__device__ __forceinline__ void mma_bf16(
    float& d0, float& d1, float& d2, float& d3,
    unsigned a0, unsigned a1, unsigned a2, unsigned a3,
    unsigned b0, unsigned b1)
{
    asm volatile(
        "mma.sync.aligned.m16n8k16.row.col.f32.bf16.bf16.f32 "
        "{%0,%1,%2,%3}, {%4,%5,%6,%7}, {%8,%9}, {%0,%1,%2,%3};\n"
        : "+f"(d0), "+f"(d1), "+f"(d2), "+f"(d3)
        : "r"(a0), "r"(a1), "r"(a2), "r"(a3), "r"(b0), "r"(b1));
}

__device__ __forceinline__ void ldsm4(unsigned& r0, unsigned& r1,
                                      unsigned& r2, unsigned& r3, uint32_t addr)
{
    asm volatile("ldmatrix.sync.aligned.m8n8.x4.shared.b16 {%0,%1,%2,%3}, [%4];"
                 : "=r"(r0), "=r"(r1), "=r"(r2), "=r"(r3) : "r"(addr));
}

__device__ __forceinline__ void ldsm2(unsigned& r0, unsigned& r1, uint32_t addr)
{
    asm volatile("ldmatrix.sync.aligned.m8n8.x2.shared.b16 {%0,%1}, [%2];"
                 : "=r"(r0), "=r"(r1) : "r"(addr));
}

__device__ __forceinline__ unsigned prmt(unsigned a, unsigned b, unsigned sel) {
    unsigned r;
    asm("prmt.b32 %0, %1, %2, %3;" : "=r"(r) : "r"(a), "r"(b), "r"(sel));
    return r;
}

__device__ __forceinline__ unsigned pack_hi2(float v0, float v1) {
    __nv_bfloat162 h = __floats2bfloat162_rn(v0, v1);
    return *reinterpret_cast<unsigned*>(&h);
}

// ---------------------------------------------------------------------------
// Split: fp32 -> bf16 hi + bf16 lo (residual)
// ---------------------------------------------------------------------------
__device__ __forceinline__ void split_store(const float* __restrict__ src,
                                            __nv_bfloat16* hi, __nv_bfloat16* lo,
                                            int i)
{
    float4 v = ((const float4*)src)[i];
    __nv_bfloat16 h0 = __float2bfloat16(v.x);
    __nv_bfloat16 h1 = __float2bfloat16(v.y);
    __nv_bfloat16 h2 = __float2bfloat16(v.z);
    __nv_bfloat16 h3 = __float2bfloat16(v.w);
    __nv_bfloat16 l0 = __float2bfloat16(v.x - __bfloat162float(h0));
    __nv_bfloat16 l1 = __float2bfloat16(v.y - __bfloat162float(h1));
    __nv_bfloat16 l2 = __float2bfloat16(v.z - __bfloat162float(h2));
    __nv_bfloat16 l3 = __float2bfloat16(v.w - __bfloat162float(h3));
    uint2 ph, pl;
    ph.x = ((uint32_t)__bfloat16_as_ushort(h1) << 16) | __bfloat16_as_ushort(h0);
    ph.y = ((uint32_t)__bfloat16_as_ushort(h3) << 16) | __bfloat16_as_ushort(h2);
    pl.x = ((uint32_t)__bfloat16_as_ushort(l1) << 16) | __bfloat16_as_ushort(l0);
    pl.y = ((uint32_t)__bfloat16_as_ushort(l3) << 16) | __bfloat16_as_ushort(l2);
    ((uint2*)hi)[i] = ph;
    ((uint2*)lo)[i] = pl;
}

__global__ void split_x_kernel(const float* __restrict__ x, int n4)
{
    int i = blockIdx.x * blockDim.x + threadIdx.x;
    if (i < n4) split_store(x, g_x_hi, g_x_lo, i);
}

__global__ void split_w_kernel(const float* __restrict__ Wq,
                               const float* __restrict__ Wk,
                               const float* __restrict__ Wv,
                               const float* __restrict__ Wp, int n4)
{
    const float* src;
    const int z = blockIdx.z;
    if (z == 0) src = Wq; else if (z == 1) src = Wk;
    else if (z == 2) src = Wv; else src = Wp;
    int i = blockIdx.x * blockDim.x + threadIdx.x;
    if (i < n4) split_store(src, g_w_hi[z], g_w_lo[z], i);
}

// ---------------------------------------------------------------------------
// bf16-3x NT GEMM: BM=BN=128, BK=32, warp tile 64x32, ldmatrix fragments,
// double-buffered smem (one __syncthreads per chunk).
// OUT_SPLIT=1: write bf16 hi/lo; OUT_SPLIT=0: fp32 C.
// ---------------------------------------------------------------------------
#define RS 20                       // uint stride per smem row
#define ST_UINTS (128 * RS)
#define GEMM_SMEM_BYTES (8 * ST_UINTS * 4)    // 2 stages x 4 tiles = 81920 B

__device__ __forceinline__ uint4 ldg16bf(const __nv_bfloat16* p, bool v) {
    if (v) return *(const uint4*)p;
    return make_uint4(0u, 0u, 0u, 0u);
}

template <int OUT_SPLIT>
__device__ __forceinline__ void gemm_bf16_body(
    const __nv_bfloat16* __restrict__ Ahi, const __nv_bfloat16* __restrict__ Alo,
    const __nv_bfloat16* __restrict__ Bhi, const __nv_bfloat16* __restrict__ Blo,
    const float* __restrict__ bias,
    float* __restrict__ C,
    __nv_bfloat16* __restrict__ Chi, __nv_bfloat16* __restrict__ Clo)
{
    extern __shared__ unsigned smem_u[];

    const int tid  = threadIdx.x;
    const int warp = tid >> 5;
    const int lane = tid & 31;
    const int g    = lane >> 2;
    const int c    = lane & 3;
    const int warpM = warp & 1;
    const int warpN = warp >> 1;

    const int bm = blockIdx.y * 128;
    const int bn = blockIdx.x * 128;

    const int ldRow = tid >> 1;
    const int half  = tid & 1;
    const int aRow  = bm + ldRow;
    const bool aValid = (aRow < MROWS);
    const size_t aOff = (size_t)(aValid ? aRow : 0) * EDIM + half * 16;
    const size_t bOff = (size_t)(bn + ldRow) * EDIM + half * 16;
    const int sBase = ldRow * RS + half * 8;

    const uint32_t smBase = (uint32_t)__cvta_generic_to_shared(smem_u);
    // ldmatrix per-lane offsets (uint units)
    const int aLd = ((lane & 7) + 8 * ((lane >> 3) & 1)) * RS + 4 * (lane >> 4);
    const int bLd = ((lane & 7) + 8 * (lane >> 4)) * RS + 4 * ((lane >> 3) & 1);

    float acc[4][4][4];
    #pragma unroll
    for (int mt = 0; mt < 4; mt++)
        #pragma unroll
        for (int nt = 0; nt < 4; nt++)
            #pragma unroll
            for (int r = 0; r < 4; r++)
                acc[mt][nt][r] = 0.0f;

    uint4 rAh[2], rAl[2], rBh[2], rBl[2];
    #pragma unroll
    for (int u = 0; u < 2; u++) {
        rAh[u] = ldg16bf(Ahi + aOff + u * 8, aValid);
        rAl[u] = ldg16bf(Alo + aOff + u * 8, aValid);
        rBh[u] = *(const uint4*)(Bhi + bOff + u * 8);
        rBl[u] = *(const uint4*)(Blo + bOff + u * 8);
    }
    // store chunk 0 into stage 0
    {
        unsigned* st = smem_u;
        #pragma unroll
        for (int u = 0; u < 2; u++) {
            *(uint4*)(st + sBase + u * 4)                = rAh[u];
            *(uint4*)(st + ST_UINTS + sBase + u * 4)     = rAl[u];
            *(uint4*)(st + 2 * ST_UINTS + sBase + u * 4) = rBh[u];
            *(uint4*)(st + 3 * ST_UINTS + sBase + u * 4) = rBl[u];
        }
    }
    __syncthreads();

    const int nCh = EDIM / 32;   // 24
    for (int ch = 0; ch < nCh; ch++) {
        const int stage = ch & 1;
        const uint32_t sAh = smBase + (stage * 4 * ST_UINTS) * 4;
        const uint32_t sAl = sAh + ST_UINTS * 4;
        const uint32_t sBh = sAl + ST_UINTS * 4;
        const uint32_t sBl = sBh + ST_UINTS * 4;

        if (ch + 1 < nCh) {
            const size_t k0 = (size_t)(ch + 1) * 32;
            #pragma unroll
            for (int u = 0; u < 2; u++) {
                rAh[u] = ldg16bf(Ahi + aOff + k0 + u * 8, aValid);
                rAl[u] = ldg16bf(Alo + aOff + k0 + u * 8, aValid);
                rBh[u] = *(const uint4*)(Bhi + bOff + k0 + u * 8);
                rBl[u] = *(const uint4*)(Blo + bOff + k0 + u * 8);
            }
        }

        #pragma unroll
        for (int ks = 0; ks < 2; ks++) {
            const int kk = ks * 8;
            unsigned ah[4][4], al[4][4], bh[4][2], bl[4][2];
            #pragma unroll
            for (int mt = 0; mt < 4; mt++) {
                const uint32_t ao = (uint32_t)(((warpM * 64 + mt * 16) * RS + kk + aLd) * 4);
                ldsm4(ah[mt][0], ah[mt][1], ah[mt][2], ah[mt][3], sAh + ao);
                ldsm4(al[mt][0], al[mt][1], al[mt][2], al[mt][3], sAl + ao);
            }
            #pragma unroll
            for (int p = 0; p < 2; p++) {
                const uint32_t bo = (uint32_t)(((warpN * 32 + p * 16) * RS + kk + bLd) * 4);
                ldsm4(bh[2 * p][0], bh[2 * p][1], bh[2 * p + 1][0], bh[2 * p + 1][1], sBh + bo);
                ldsm4(bl[2 * p][0], bl[2 * p][1], bl[2 * p + 1][0], bl[2 * p + 1][1], sBl + bo);
            }
            #pragma unroll
            for (int mt = 0; mt < 4; mt++)
                #pragma unroll
                for (int nt = 0; nt < 4; nt++) {
                    float* d = acc[mt][nt];
                    mma_bf16(d[0], d[1], d[2], d[3],
                             ah[mt][0], ah[mt][1], ah[mt][2], ah[mt][3],
                             bh[nt][0], bh[nt][1]);
                    mma_bf16(d[0], d[1], d[2], d[3],
                             ah[mt][0], ah[mt][1], ah[mt][2], ah[mt][3],
                             bl[nt][0], bl[nt][1]);
                    mma_bf16(d[0], d[1], d[2], d[3],
                             al[mt][0], al[mt][1], al[mt][2], al[mt][3],
                             bh[nt][0], bh[nt][1]);
                }
        }

        if (ch + 1 < nCh) {
            unsigned* st = smem_u + ((ch + 1) & 1) * 4 * ST_UINTS;
            #pragma unroll
            for (int u = 0; u < 2; u++) {
                *(uint4*)(st + sBase + u * 4)                = rAh[u];
                *(uint4*)(st + ST_UINTS + sBase + u * 4)     = rAl[u];
                *(uint4*)(st + 2 * ST_UINTS + sBase + u * 4) = rBh[u];
                *(uint4*)(st + 3 * ST_UINTS + sBase + u * 4) = rBl[u];
            }
        }
        __syncthreads();
    }

    // epilogue
    #pragma unroll
    for (int mt = 0; mt < 4; mt++) {
        const int row0 = bm + warpM * 64 + mt * 16 + g;
        const int row1 = row0 + 8;
        #pragma unroll
        for (int nt = 0; nt < 4; nt++) {
            const int col = bn + warpN * 32 + nt * 8 + 2 * c;
            const float b0 = bias[col];
            const float b1 = bias[col + 1];
            float v00 = acc[mt][nt][0] + b0, v01 = acc[mt][nt][1] + b1;
            float v10 = acc[mt][nt][2] + b0, v11 = acc[mt][nt][3] + b1;
            if (OUT_SPLIT) {
                if (row0 < MROWS) {
                    size_t ui = ((size_t)row0 * EDIM + col) >> 1;
                    float h0 = __bfloat162float(__float2bfloat16(v00));
                    float h1 = __bfloat162float(__float2bfloat16(v01));
                    ((unsigned*)Chi)[ui] = pack_hi2(v00, v01);
                    ((unsigned*)Clo)[ui] = pack_hi2(v00 - h0, v01 - h1);
                }
                if (row1 < MROWS) {
                    size_t ui = ((size_t)row1 * EDIM + col) >> 1;
                    float h0 = __bfloat162float(__float2bfloat16(v10));
                    float h1 = __bfloat162float(__float2bfloat16(v11));
                    ((unsigned*)Chi)[ui] = pack_hi2(v10, v11);
                    ((unsigned*)Clo)[ui] = pack_hi2(v10 - h0, v11 - h1);
                }
            } else {
                if (row0 < MROWS)
                    *(float2*)(C + (size_t)row0 * EDIM + col) = make_float2(v00, v01);
                if (row1 < MROWS)
                    *(float2*)(C + (size_t)row1 * EDIM + col) = make_float2(v10, v11);
            }
        }
    }
}

__global__ __launch_bounds__(256, 1) void qkv_gemm_kernel(
    const float* __restrict__ bq, const float* __restrict__ bk,
    const float* __restrict__ bv)
{
    const __nv_bfloat16 *wh, *wl;
    const float* bias;
    __nv_bfloat16 *ch, *cl;
    if (blockIdx.z == 0)      { wh = g_w_hi[0]; wl = g_w_lo[0]; bias = bq; ch = g_q_hi; cl = g_q_lo; }
    else if (blockIdx.z == 1) { wh = g_w_hi[1]; wl = g_w_lo[1]; bias = bk; ch = g_k_hi; cl = g_k_lo; }
    else                      { wh = g_w_hi[2]; wl = g_w_lo[2]; bias = bv; ch = g_v_hi; cl = g_v_lo; }
    gemm_bf16_body<1>(g_x_hi, g_x_lo, wh, wl, bias, nullptr, ch, cl);
}

__global__ __launch_bounds__(256, 1) void proj_gemm_kernel(
    const float* __restrict__ bp, float* __restrict__ out)
{
    gemm_bf16_body<0>(g_ao_hi, g_ao_lo, g_w_hi[3], g_w_lo[3], bp, out, nullptr, nullptr);
}

// ---------------------------------------------------------------------------
// Attention via mma.sync bf16-3x + ldmatrix. One CTA per (b,h), 256 threads.
// ---------------------------------------------------------------------------
#define SP   224
#define KSU  36
#define VSU  116
#define ES   232

#define SM_KH   0
#define SM_KL   (SM_KH + SP * KSU)
#define SM_VTH  (SM_KL + SP * KSU)
#define SM_VTL  (SM_VTH + 64 * VSU)
#define SM_QH   (SM_VTL + 64 * VSU)
#define SM_QL   (SM_QH + 32 * KSU)
#define SM_E    (SM_QL + 32 * KSU)
#define SM_PH   (SM_E + 32 * ES)
#define SM_PL   (SM_PH + 32 * VSU)
#define ATTN_SMEM_WORDS (SM_PL + 32 * VSU)
#define ATTN_SMEM_BYTES (ATTN_SMEM_WORDS * 4)    // 192512

__global__ __launch_bounds__(256, 1) void attn_kernel()
{
    extern __shared__ unsigned smw[];
    unsigned* Kh  = smw + SM_KH;
    unsigned* Kl  = smw + SM_KL;
    unsigned* Vth = smw + SM_VTH;
    unsigned* Vtl = smw + SM_VTL;
    unsigned* Qh  = smw + SM_QH;
    unsigned* Ql  = smw + SM_QL;
    float*    E   = (float*)(smw + SM_E);
    unsigned* Ph  = smw + SM_PH;
    unsigned* Pl  = smw + SM_PL;

    const int bh = blockIdx.x;
    const int b = bh / NH;
    const int h = bh % NH;
    const size_t base = (size_t)b * PERB + (size_t)h * PERH;

    const unsigned* Qgh = (const unsigned*)g_q_hi + (base >> 1);
    const unsigned* Qgl = (const unsigned*)g_q_lo + (base >> 1);
    const unsigned* Kgh = (const unsigned*)g_k_hi + (base >> 1);
    const unsigned* Kgl = (const unsigned*)g_k_lo + (base >> 1);
    const unsigned* Vgh = (const unsigned*)g_v_hi + (base >> 1);
    const unsigned* Vgl = (const unsigned*)g_v_lo + (base >> 1);
    unsigned* AOh = (unsigned*)g_ao_hi + (base >> 1);
    unsigned* AOl = (unsigned*)g_ao_lo + (base >> 1);

    const int tid  = threadIdx.x;
    const int warp = tid >> 5;
    const int lane = tid & 31;
    const int g    = lane >> 2;
    const int c    = lane & 3;
    const int wM   = warp & 1;
    const int wN   = warp >> 1;

    const uint32_t smBase = (uint32_t)__cvta_generic_to_shared(smw);
    const uint32_t sKh  = smBase + SM_KH  * 4;
    const uint32_t sKl  = smBase + SM_KL  * 4;
    const uint32_t sVth = smBase + SM_VTH * 4;
    const uint32_t sVtl = smBase + SM_VTL * 4;
    const uint32_t sQh  = smBase + SM_QH  * 4;
    const uint32_t sQl  = smBase + SM_QL  * 4;
    const uint32_t sPh  = smBase + SM_PH  * 4;
    const uint32_t sPl  = smBase + SM_PL  * 4;

    // ldmatrix lane offsets (uint units)
    const int aLdK = ((lane & 7) + 8 * ((lane >> 3) & 1)) * KSU + 4 * (lane >> 4); // A, stride KSU
    const int bLdK = ((lane & 7) + 8 * (lane >> 4)) * KSU + 4 * ((lane >> 3) & 1); // B x4, stride KSU
    const int bLdK2 = (lane & 7) * KSU + 4 * ((lane >> 3) & 1);                    // B x2, stride KSU
    const int aLdV = ((lane & 7) + 8 * ((lane >> 3) & 1)) * VSU + 4 * (lane >> 4); // A, stride VSU
    const int bLdV = ((lane & 7) + 8 * (lane >> 4)) * VSU + 4 * ((lane >> 3) & 1); // B x4, stride VSU

    // zero K/V region (covers pad rows/cols)
    for (int i = tid; i < (SP * KSU * 2 + 64 * VSU * 2) / 4; i += 256)
        ((uint4*)smw)[i] = make_uint4(0u, 0u, 0u, 0u);
    __syncthreads();

    // K fill
    for (int t = tid; t < 197 * 8; t += 256) {
        int row = t >> 3, chk = t & 7;
        uint4 vh = *(const uint4*)(Kgh + row * 32 + chk * 4);
        uint4 vl = *(const uint4*)(Kgl + row * 32 + chk * 4);
        *(uint4*)(Kh + row * KSU + chk * 4) = vh;
        *(uint4*)(Kl + row * KSU + chk * 4) = vl;
    }
    // Vt fill (transpose + repack along j)
    for (int t = tid; t < 99 * 8; t += 256) {
        int j2 = t >> 3, dch = t & 7;
        int j0 = 2 * j2;
        uint4 ah = *(const uint4*)(Vgh + j0 * 32 + dch * 4);
        uint4 al = *(const uint4*)(Vgl + j0 * 32 + dch * 4);
        uint4 bhv = make_uint4(0u, 0u, 0u, 0u), blv = bhv;
        if (j0 + 1 < SEQ) {
            bhv = *(const uint4*)(Vgh + (j0 + 1) * 32 + dch * 4);
            blv = *(const uint4*)(Vgl + (j0 + 1) * 32 + dch * 4);
        }
        const unsigned* av[2] = {&ah.x, &al.x};
        const unsigned* bv[2] = {&bhv.x, &blv.x};
        unsigned* dst[2] = {Vth, Vtl};
        #pragma unroll
        for (int s = 0; s < 2; s++) {
            #pragma unroll
            for (int i = 0; i < 4; i++) {
                int d = dch * 8 + 2 * i;
                dst[s][(d    ) * VSU + j2] = prmt(av[s][i], bv[s][i], 0x5410);
                dst[s][(d + 1) * VSU + j2] = prmt(av[s][i], bv[s][i], 0x7632);
            }
        }
    }
    __syncthreads();

    for (int stripe = 0; stripe < 7; stripe++) {
        const int rbase = stripe * 32;

        // load Q stripe
        {
            int row = tid >> 3, chk = tid & 7;
            int rg = rbase + row;
            uint4 vh = make_uint4(0u, 0u, 0u, 0u), vl = vh;
            if (rg < SEQ) {
                vh = *(const uint4*)(Qgh + rg * 32 + chk * 4);
                vl = *(const uint4*)(Qgl + rg * 32 + chk * 4);
            }
            *(uint4*)(Qh + row * KSU + chk * 4) = vh;
            *(uint4*)(Ql + row * KSU + chk * 4) = vl;
        }
        __syncthreads();

        // ---- E = Q_stripe @ K^T ----
        {
            float e[7][4];
            #pragma unroll
            for (int t = 0; t < 7; t++)
                #pragma unroll
                for (int r = 0; r < 4; r++) e[t][r] = 0.f;

            #pragma unroll
            for (int ks = 0; ks < 4; ks++) {
                const int kk = ks * 8;
                unsigned ah0, ah1, ah2, ah3, al0, al1, al2, al3;
                {
                    const uint32_t ao = (uint32_t)((wM * 16 * KSU + kk + aLdK) * 4);
                    ldsm4(ah0, ah1, ah2, ah3, sQh + ao);
                    ldsm4(al0, al1, al2, al3, sQl + ao);
                }
                unsigned bh[7][2], bl[7][2];
                #pragma unroll
                for (int p = 0; p < 3; p++) {
                    const uint32_t bo = (uint32_t)(((wN * 56 + p * 16) * KSU + kk + bLdK) * 4);
                    ldsm4(bh[2 * p][0], bh[2 * p][1], bh[2 * p + 1][0], bh[2 * p + 1][1], sKh + bo);
                    ldsm4(bl[2 * p][0], bl[2 * p][1], bl[2 * p + 1][0], bl[2 * p + 1][1], sKl + bo);
                }
                {
                    const uint32_t bo = (uint32_t)(((wN * 56 + 48) * KSU + kk + bLdK2) * 4);
                    ldsm2(bh[6][0], bh[6][1], sKh + bo);
                    ldsm2(bl[6][0], bl[6][1], sKl + bo);
                }
                #pragma unroll
                for (int t = 0; t < 7; t++) {
                    mma_bf16(e[t][0], e[t][1], e[t][2], e[t][3],
                             ah0, ah1, ah2, ah3, bh[t][0], bh[t][1]);
                    mma_bf16(e[t][0], e[t][1], e[t][2], e[t][3],
                             ah0, ah1, ah2, ah3, bl[t][0], bl[t][1]);
                    mma_bf16(e[t][0], e[t][1], e[t][2], e[t][3],
                             al0, al1, al2, al3, bh[t][0], bh[t][1]);
                }
            }
            #pragma unroll
            for (int t = 0; t < 7; t++) {
                const int col = wN * 56 + t * 8 + 2 * c;
                const int row = wM * 16 + g;
                *(float2*)(E + row * ES + col)       = make_float2(e[t][0], e[t][1]);
                *(float2*)(E + (row + 8) * ES + col) = make_float2(e[t][2], e[t][3]);
            }
        }
        __syncthreads();

        // ---- softmax rows (warp w owns rows 4w..4w+3), write P hi/lo ----
        {
            #pragma unroll
            for (int rr = 0; rr < 4; rr++) {
                const int row = warp * 4 + rr;
                const float* er = E + row * ES;
                float e0[4], e1[4];
                float mx = -1e30f;
                int cnt = 0;
                for (int p2 = lane; p2 < 112; p2 += 32, cnt++) {
                    float2 ev = *(const float2*)(er + 2 * p2);
                    e0[cnt] = (2 * p2     < SEQ) ? ev.x : -1e30f;
                    e1[cnt] = (2 * p2 + 1 < SEQ) ? ev.y : -1e30f;
                    mx = fmaxf(mx, fmaxf(e0[cnt], e1[cnt]));
                }
                #pragma unroll
                for (int o = 16; o > 0; o >>= 1)
                    mx = fmaxf(mx, __shfl_xor_sync(0xffffffffu, mx, o));
                float sum = 0.f;
                #pragma unroll
                for (int i = 0; i < 4; i++) {
                    if (i < cnt) {
                        e0[i] = __expf(e0[i] - mx);
                        e1[i] = __expf(e1[i] - mx);
                        sum += e0[i] + e1[i];
                    }
                }
                #pragma unroll
                for (int o = 16; o > 0; o >>= 1)
                    sum += __shfl_xor_sync(0xffffffffu, sum, o);
                const float inv = 1.0f / (sum * 27.712812921102035f);  // sqrt(768)
                cnt = 0;
                for (int p2 = lane; p2 < 112; p2 += 32, cnt++) {
                    float p0 = e0[cnt] * inv;
                    float p1 = e1[cnt] * inv;
                    float h0 = __bfloat162float(__float2bfloat16(p0));
                    float h1 = __bfloat162float(__float2bfloat16(p1));
                    Ph[row * VSU + p2] = pack_hi2(p0, p1);
                    Pl[row * VSU + p2] = pack_hi2(p0 - h0, p1 - h1);
                }
            }
        }
        __syncthreads();

        // ---- O_stripe = P @ V ----
        {
            float o[2][4];
            #pragma unroll
            for (int t = 0; t < 2; t++)
                #pragma unroll
                for (int r = 0; r < 4; r++) o[t][r] = 0.f;

            #pragma unroll 2
            for (int ks = 0; ks < 14; ks++) {
                const int kk = ks * 8;
                unsigned ah0, ah1, ah2, ah3, al0, al1, al2, al3;
                {
                    const uint32_t ao = (uint32_t)((wM * 16 * VSU + kk + aLdV) * 4);
                    ldsm4(ah0, ah1, ah2, ah3, sPh + ao);
                    ldsm4(al0, al1, al2, al3, sPl + ao);
                }
                unsigned bh[2][2], bl[2][2];
                {
                    const uint32_t bo = (uint32_t)((wN * 16 * VSU + kk + bLdV) * 4);
                    ldsm4(bh[0][0], bh[0][1], bh[1][0], bh[1][1], sVth + bo);
                    ldsm4(bl[0][0], bl[0][1], bl[1][0], bl[1][1], sVtl + bo);
                }
                #pragma unroll
                for (int t = 0; t < 2; t++) {
                    mma_bf16(o[t][0], o[t][1], o[t][2], o[t][3],
                             ah0, ah1, ah2, ah3, bh[t][0], bh[t][1]);
                    mma_bf16(o[t][0], o[t][1], o[t][2], o[t][3],
                             ah0, ah1, ah2, ah3, bl[t][0], bl[t][1]);
                    mma_bf16(o[t][0], o[t][1], o[t][2], o[t][3],
                             al0, al1, al2, al3, bh[t][0], bh[t][1]);
                }
            }
            #pragma unroll
            for (int t = 0; t < 2; t++) {
                const int col = wN * 16 + t * 8 + 2 * c;
                const int rg0 = rbase + wM * 16 + g;
                const int rg1 = rg0 + 8;
                if (rg0 < SEQ) {
                    float h0 = __bfloat162float(__float2bfloat16(o[t][0]));
                    float h1 = __bfloat162float(__float2bfloat16(o[t][1]));
                    AOh[(rg0 * HD + col) >> 1] = pack_hi2(o[t][0], o[t][1]);
                    AOl[(rg0 * HD + col) >> 1] = pack_hi2(o[t][0] - h0, o[t][1] - h1);
                }
                if (rg1 < SEQ) {
                    float h0 = __bfloat162float(__float2bfloat16(o[t][2]));
                    float h1 = __bfloat162float(__float2bfloat16(o[t][3]));
                    AOh[(rg1 * HD + col) >> 1] = pack_hi2(o[t][2], o[t][3]);
                    AOl[(rg1 * HD + col) >> 1] = pack_hi2(o[t][2] - h0, o[t][3] - h1);
                }
            }
        }
        __syncthreads();
    }
}

// ---------------------------------------------------------------------------
// Launch
// ---------------------------------------------------------------------------
extern "C" void kernel_launch(void* const* d_in, const int* in_sizes, int n_in,
                              void* d_out, int out_size)
{
    const float* x  = (const float*)d_in[0];
    const float* Wq = (const float*)d_in[1];
    const float* bq = (const float*)d_in[2];
    const float* Wk = (const float*)d_in[3];
    const float* bk = (const float*)d_in[4];
    const float* Wv = (const float*)d_in[5];
    const float* bv = (const float*)d_in[6];
    const float* Wp = (const float*)d_in[7];
    const float* bp = (const float*)d_in[8];
    float* out = (float*)d_out;

    cudaFuncSetAttribute(qkv_gemm_kernel,
                         cudaFuncAttributeMaxDynamicSharedMemorySize,
                         GEMM_SMEM_BYTES);
    cudaFuncSetAttribute(proj_gemm_kernel,
                         cudaFuncAttributeMaxDynamicSharedMemorySize,
                         GEMM_SMEM_BYTES);
    cudaFuncSetAttribute(attn_kernel,
                         cudaFuncAttributeMaxDynamicSharedMemorySize,
                         ATTN_SMEM_BYTES);

    const int n4x = MROWS * EDIM / 4;
    const int n4w = EDIM * EDIM / 4;
    split_x_kernel<<<(n4x + 255) / 256, 256>>>(x, n4x);
    dim3 gridW((n4w + 255) / 256, 1, 4);
    split_w_kernel<<<gridW, 256>>>(Wq, Wk, Wv, Wp, n4w);

    dim3 gridQKV(EDIM / 128, (MROWS + 127) / 128, 3);   // (6, 99, 3)
    qkv_gemm_kernel<<<gridQKV, 256, GEMM_SMEM_BYTES>>>(bq, bk, bv);

    attn_kernel<<<BATCH * NH, 256, ATTN_SMEM_BYTES>>>();

    dim3 gridP(EDIM / 128, (MROWS + 127) / 128, 1);     // (6, 99)
    proj_gemm_kernel<<<gridP, 256, GEMM_SMEM_BYTES>>>(bp, out);
}

// round 9
// speedup vs baseline: 2.8374x; 1.0991x over previous
#include <cuda_runtime.h>
#include <cuda_bf16.h>
#include <cstdint>

// Problem constants
#define BATCH 64
#define SEQ   197
#define EDIM  768
#define NH    12
#define HD    64
#define MROWS (BATCH * SEQ)          // 12608
#define PERB  (SEQ * EDIM)
#define PERH  (SEQ * HD)

// bf16 split operands (hi + residual lo ~= 16 mantissa bits)
__device__ __align__(16) __nv_bfloat16 g_x_hi[MROWS * EDIM];
__device__ __align__(16) __nv_bfloat16 g_x_lo[MROWS * EDIM];
__device__ __align__(16) __nv_bfloat16 g_w_hi[4][EDIM * EDIM];   // q,k,v,p
__device__ __align__(16) __nv_bfloat16 g_w_lo[4][EDIM * EDIM];
__device__ __align__(16) __nv_bfloat16 g_q_hi[MROWS * EDIM];
__device__ __align__(16) __nv_bfloat16 g_q_lo[MROWS * EDIM];
__device__ __align__(16) __nv_bfloat16 g_k_hi[MROWS * EDIM];
__device__ __align__(16) __nv_bfloat16 g_k_lo[MROWS * EDIM];
__device__ __align__(16) __nv_bfloat16 g_v_hi[MROWS * EDIM];
__device__ __align__(16) __nv_bfloat16 g_v_lo[MROWS * EDIM];
__device__ __align__(16) __nv_bfloat16 g_ao_hi[MROWS * EDIM];
__device__ __align__(16) __nv_bfloat16 g_ao_lo[MROWS * EDIM];

// ---------------------------------------------------------------------------
// mma / ldmatrix / cp.async helpers (all legal on plain compute_103 target)
// ---------------------------------------------------------------------------
__device__ __forceinline__ void mma_bf16(
    float& d0, float& d1, float& d2, float& d3,
    unsigned a0, unsigned a1, unsigned a2, unsigned a3,
    unsigned b0, unsigned b1)
{
    asm volatile(
        "mma.sync.aligned.m16n8k16.row.col.f32.bf16.bf16.f32 "
        "{%0,%1,%2,%3}, {%4,%5,%6,%7}, {%8,%9}, {%0,%1,%2,%3};\n"
        : "+f"(d0), "+f"(d1), "+f"(d2), "+f"(d3)
        : "r"(a0), "r"(a1), "r"(a2), "r"(a3), "r"(b0), "r"(b1));
}

__device__ __forceinline__ void ldsm4(unsigned& r0, unsigned& r1,
                                      unsigned& r2, unsigned& r3, uint32_t addr)
{
    asm volatile("ldmatrix.sync.aligned.m8n8.x4.shared.b16 {%0,%1,%2,%3}, [%4];"
                 : "=r"(r0), "=r"(r1), "=r"(r2), "=r"(r3) : "r"(addr));
}

__device__ __forceinline__ void ldsm2(unsigned& r0, unsigned& r1, uint32_t addr)
{
    asm volatile("ldmatrix.sync.aligned.m8n8.x2.shared.b16 {%0,%1}, [%2];"
                 : "=r"(r0), "=r"(r1) : "r"(addr));
}

__device__ __forceinline__ void cp_async16(uint32_t dst, const void* src, int srcSz)
{
    asm volatile("cp.async.cg.shared.global [%0], [%1], 16, %2;"
                 :: "r"(dst), "l"(src), "r"(srcSz) : "memory");
}
#define CP_COMMIT() asm volatile("cp.async.commit_group;" ::: "memory")
#define CP_WAIT0()  asm volatile("cp.async.wait_group 0;" ::: "memory")

__device__ __forceinline__ unsigned prmt(unsigned a, unsigned b, unsigned sel) {
    unsigned r;
    asm("prmt.b32 %0, %1, %2, %3;" : "=r"(r) : "r"(a), "r"(b), "r"(sel));
    return r;
}

__device__ __forceinline__ unsigned pack_hi2(float v0, float v1) {
    __nv_bfloat162 h = __floats2bfloat162_rn(v0, v1);
    return *reinterpret_cast<unsigned*>(&h);
}

// ---------------------------------------------------------------------------
// Split: fp32 -> bf16 hi + bf16 lo (residual)
// ---------------------------------------------------------------------------
__device__ __forceinline__ void split_store(const float* __restrict__ src,
                                            __nv_bfloat16* hi, __nv_bfloat16* lo,
                                            int i)
{
    float4 v = ((const float4*)src)[i];
    __nv_bfloat16 h0 = __float2bfloat16(v.x);
    __nv_bfloat16 h1 = __float2bfloat16(v.y);
    __nv_bfloat16 h2 = __float2bfloat16(v.z);
    __nv_bfloat16 h3 = __float2bfloat16(v.w);
    __nv_bfloat16 l0 = __float2bfloat16(v.x - __bfloat162float(h0));
    __nv_bfloat16 l1 = __float2bfloat16(v.y - __bfloat162float(h1));
    __nv_bfloat16 l2 = __float2bfloat16(v.z - __bfloat162float(h2));
    __nv_bfloat16 l3 = __float2bfloat16(v.w - __bfloat162float(h3));
    uint2 ph, pl;
    ph.x = ((uint32_t)__bfloat16_as_ushort(h1) << 16) | __bfloat16_as_ushort(h0);
    ph.y = ((uint32_t)__bfloat16_as_ushort(h3) << 16) | __bfloat16_as_ushort(h2);
    pl.x = ((uint32_t)__bfloat16_as_ushort(l1) << 16) | __bfloat16_as_ushort(l0);
    pl.y = ((uint32_t)__bfloat16_as_ushort(l3) << 16) | __bfloat16_as_ushort(l2);
    ((uint2*)hi)[i] = ph;
    ((uint2*)lo)[i] = pl;
}

__global__ void split_x_kernel(const float* __restrict__ x, int n4)
{
    int i = blockIdx.x * blockDim.x + threadIdx.x;
    if (i < n4) split_store(x, g_x_hi, g_x_lo, i);
}

__global__ void split_w_kernel(const float* __restrict__ Wq,
                               const float* __restrict__ Wk,
                               const float* __restrict__ Wv,
                               const float* __restrict__ Wp, int n4)
{
    const float* src;
    const int z = blockIdx.z;
    if (z == 0) src = Wq; else if (z == 1) src = Wk;
    else if (z == 2) src = Wv; else src = Wp;
    int i = blockIdx.x * blockDim.x + threadIdx.x;
    if (i < n4) split_store(src, g_w_hi[z], g_w_lo[z], i);
}

// ---------------------------------------------------------------------------
// bf16-3x NT GEMM: BM=BN=128, BK=32, warp tile 64x32, ldmatrix + cp.async,
// double-buffered. __launch_bounds__(256,2): 2 CTAs/SM for latency hiding.
// ---------------------------------------------------------------------------
#define RS 20                       // uint stride per smem row
#define ST_UINTS (128 * RS)
#define GEMM_SMEM_BYTES (8 * ST_UINTS * 4)    // 2 stages x 4 tiles = 81920 B

template <int OUT_SPLIT>
__device__ __forceinline__ void gemm_bf16_body(
    const __nv_bfloat16* __restrict__ Ahi, const __nv_bfloat16* __restrict__ Alo,
    const __nv_bfloat16* __restrict__ Bhi, const __nv_bfloat16* __restrict__ Blo,
    const float* __restrict__ bias,
    float* __restrict__ C,
    __nv_bfloat16* __restrict__ Chi, __nv_bfloat16* __restrict__ Clo)
{
    extern __shared__ unsigned smem_u[];

    const int tid  = threadIdx.x;
    const int warp = tid >> 5;
    const int lane = tid & 31;
    const int g    = lane >> 2;
    const int c    = lane & 3;
    const int warpM = warp & 1;
    const int warpN = warp >> 1;

    const int bm = blockIdx.y * 128;
    const int bn = blockIdx.x * 128;

    const int ldRow = tid >> 1;
    const int half  = tid & 1;
    const int aRow  = bm + ldRow;
    const bool aValid = (aRow < MROWS);
    const int aSz = aValid ? 16 : 0;
    const size_t aOff = (size_t)(aValid ? aRow : 0) * EDIM + half * 16;
    const size_t bOff = (size_t)(bn + ldRow) * EDIM + half * 16;
    const int sBase = ldRow * RS + half * 8;

    const uint32_t smBase = (uint32_t)__cvta_generic_to_shared(smem_u);
    const int aLd = ((lane & 7) + 8 * ((lane >> 3) & 1)) * RS + 4 * (lane >> 4);
    const int bLd = ((lane & 7) + 8 * (lane >> 4)) * RS + 4 * ((lane >> 3) & 1);

    float acc[4][4][4];
    #pragma unroll
    for (int mt = 0; mt < 4; mt++)
        #pragma unroll
        for (int nt = 0; nt < 4; nt++)
            #pragma unroll
            for (int r = 0; r < 4; r++)
                acc[mt][nt][r] = 0.0f;

    // issue chunk ch into stage
    auto issue = [&](int ch, int stage) {
        const size_t k0 = (size_t)ch * 32;
        const uint32_t st = smBase + (uint32_t)(stage * 4 * ST_UINTS) * 4;
        #pragma unroll
        for (int u = 0; u < 2; u++) {
            cp_async16(st + (uint32_t)(sBase + u * 4) * 4,                Ahi + aOff + k0 + u * 8, aSz);
            cp_async16(st + (uint32_t)(ST_UINTS + sBase + u * 4) * 4,     Alo + aOff + k0 + u * 8, aSz);
            cp_async16(st + (uint32_t)(2 * ST_UINTS + sBase + u * 4) * 4, Bhi + bOff + k0 + u * 8, 16);
            cp_async16(st + (uint32_t)(3 * ST_UINTS + sBase + u * 4) * 4, Blo + bOff + k0 + u * 8, 16);
        }
        CP_COMMIT();
    };

    issue(0, 0);

    const int nCh = EDIM / 32;   // 24
    for (int ch = 0; ch < nCh; ch++) {
        const int stage = ch & 1;
        CP_WAIT0();
        __syncthreads();          // chunk ch in smem; all warps done with other stage
        if (ch + 1 < nCh) issue(ch + 1, stage ^ 1);

        const uint32_t sAh = smBase + (uint32_t)(stage * 4 * ST_UINTS) * 4;
        const uint32_t sAl = sAh + ST_UINTS * 4;
        const uint32_t sBh = sAl + ST_UINTS * 4;
        const uint32_t sBl = sBh + ST_UINTS * 4;

        #pragma unroll
        for (int ks = 0; ks < 2; ks++) {
            const int kk = ks * 8;
            unsigned ah[4][4], al[4][4], bh[4][2], bl[4][2];
            #pragma unroll
            for (int mt = 0; mt < 4; mt++) {
                const uint32_t ao = (uint32_t)(((warpM * 64 + mt * 16) * RS + kk + aLd) * 4);
                ldsm4(ah[mt][0], ah[mt][1], ah[mt][2], ah[mt][3], sAh + ao);
                ldsm4(al[mt][0], al[mt][1], al[mt][2], al[mt][3], sAl + ao);
            }
            #pragma unroll
            for (int p = 0; p < 2; p++) {
                const uint32_t bo = (uint32_t)(((warpN * 32 + p * 16) * RS + kk + bLd) * 4);
                ldsm4(bh[2 * p][0], bh[2 * p][1], bh[2 * p + 1][0], bh[2 * p + 1][1], sBh + bo);
                ldsm4(bl[2 * p][0], bl[2 * p][1], bl[2 * p + 1][0], bl[2 * p + 1][1], sBl + bo);
            }
            #pragma unroll
            for (int mt = 0; mt < 4; mt++)
                #pragma unroll
                for (int nt = 0; nt < 4; nt++) {
                    float* d = acc[mt][nt];
                    mma_bf16(d[0], d[1], d[2], d[3],
                             ah[mt][0], ah[mt][1], ah[mt][2], ah[mt][3],
                             bh[nt][0], bh[nt][1]);
                    mma_bf16(d[0], d[1], d[2], d[3],
                             ah[mt][0], ah[mt][1], ah[mt][2], ah[mt][3],
                             bl[nt][0], bl[nt][1]);
                    mma_bf16(d[0], d[1], d[2], d[3],
                             al[mt][0], al[mt][1], al[mt][2], al[mt][3],
                             bh[nt][0], bh[nt][1]);
                }
        }
        __syncthreads();          // done reading this stage before it is refilled
    }

    // epilogue
    #pragma unroll
    for (int mt = 0; mt < 4; mt++) {
        const int row0 = bm + warpM * 64 + mt * 16 + g;
        const int row1 = row0 + 8;
        #pragma unroll
        for (int nt = 0; nt < 4; nt++) {
            const int col = bn + warpN * 32 + nt * 8 + 2 * c;
            const float b0 = bias[col];
            const float b1 = bias[col + 1];
            float v00 = acc[mt][nt][0] + b0, v01 = acc[mt][nt][1] + b1;
            float v10 = acc[mt][nt][2] + b0, v11 = acc[mt][nt][3] + b1;
            if (OUT_SPLIT) {
                if (row0 < MROWS) {
                    size_t ui = ((size_t)row0 * EDIM + col) >> 1;
                    float h0 = __bfloat162float(__float2bfloat16(v00));
                    float h1 = __bfloat162float(__float2bfloat16(v01));
                    ((unsigned*)Chi)[ui] = pack_hi2(v00, v01);
                    ((unsigned*)Clo)[ui] = pack_hi2(v00 - h0, v01 - h1);
                }
                if (row1 < MROWS) {
                    size_t ui = ((size_t)row1 * EDIM + col) >> 1;
                    float h0 = __bfloat162float(__float2bfloat16(v10));
                    float h1 = __bfloat162float(__float2bfloat16(v11));
                    ((unsigned*)Chi)[ui] = pack_hi2(v10, v11);
                    ((unsigned*)Clo)[ui] = pack_hi2(v10 - h0, v11 - h1);
                }
            } else {
                if (row0 < MROWS)
                    *(float2*)(C + (size_t)row0 * EDIM + col) = make_float2(v00, v01);
                if (row1 < MROWS)
                    *(float2*)(C + (size_t)row1 * EDIM + col) = make_float2(v10, v11);
            }
        }
    }
}

__global__ __launch_bounds__(256, 2) void qkv_gemm_kernel(
    const float* __restrict__ bq, const float* __restrict__ bk,
    const float* __restrict__ bv)
{
    const __nv_bfloat16 *wh, *wl;
    const float* bias;
    __nv_bfloat16 *ch, *cl;
    if (blockIdx.z == 0)      { wh = g_w_hi[0]; wl = g_w_lo[0]; bias = bq; ch = g_q_hi; cl = g_q_lo; }
    else if (blockIdx.z == 1) { wh = g_w_hi[1]; wl = g_w_lo[1]; bias = bk; ch = g_k_hi; cl = g_k_lo; }
    else                      { wh = g_w_hi[2]; wl = g_w_lo[2]; bias = bv; ch = g_v_hi; cl = g_v_lo; }
    gemm_bf16_body<1>(g_x_hi, g_x_lo, wh, wl, bias, nullptr, ch, cl);
}

__global__ __launch_bounds__(256, 2) void proj_gemm_kernel(
    const float* __restrict__ bp, float* __restrict__ out)
{
    gemm_bf16_body<0>(g_ao_hi, g_ao_lo, g_w_hi[3], g_w_lo[3], bp, out, nullptr, nullptr);
}

// ---------------------------------------------------------------------------
// Attention: mma.sync bf16-3x + ldmatrix, 512 threads (16 warps), 64-row
// stripes (4 per head). P overlays the E buffer (safe: E values are held in
// registers past the shfl reductions before P is written).
// ---------------------------------------------------------------------------
#define SP   224
#define KSU  36          // uint stride, K/Q rows
#define VSU  116         // uint stride, Vt rows
#define EPS  236         // word stride, E rows (fp32) / P rows (uints)
#define PLOFF 120        // Pl offset within an E/P row (uints, 16B aligned)

#define SM_KH   0
#define SM_KL   (SM_KH + SP * KSU)                // 8064
#define SM_VTH  (SM_KL + SP * KSU)                // 16128
#define SM_VTL  (SM_VTH + 64 * VSU)               // 23552
#define SM_QH   (SM_VTL + 64 * VSU)               // 30976
#define SM_QL   (SM_QH + 64 * KSU)                // 33280
#define SM_EP   (SM_QL + 64 * KSU)                // 35584
#define ATTN_SMEM_WORDS (SM_EP + 64 * EPS)        // 50688
#define ATTN_SMEM_BYTES (ATTN_SMEM_WORDS * 4)     // 202752

__global__ __launch_bounds__(512, 1) void attn_kernel()
{
    extern __shared__ unsigned smw[];
    unsigned* Kh  = smw + SM_KH;
    unsigned* Kl  = smw + SM_KL;
    unsigned* Vth = smw + SM_VTH;
    unsigned* Vtl = smw + SM_VTL;
    unsigned* Qh  = smw + SM_QH;
    unsigned* Ql  = smw + SM_QL;
    float*    E   = (float*)(smw + SM_EP);
    unsigned* Pu  = smw + SM_EP;     // P overlays E

    const int bh = blockIdx.x;
    const int b = bh / NH;
    const int h = bh % NH;
    const size_t base = (size_t)b * PERB + (size_t)h * PERH;

    const unsigned* Qgh = (const unsigned*)g_q_hi + (base >> 1);
    const unsigned* Qgl = (const unsigned*)g_q_lo + (base >> 1);
    const unsigned* Kgh = (const unsigned*)g_k_hi + (base >> 1);
    const unsigned* Kgl = (const unsigned*)g_k_lo + (base >> 1);
    const unsigned* Vgh = (const unsigned*)g_v_hi + (base >> 1);
    const unsigned* Vgl = (const unsigned*)g_v_lo + (base >> 1);
    unsigned* AOh = (unsigned*)g_ao_hi + (base >> 1);
    unsigned* AOl = (unsigned*)g_ao_lo + (base >> 1);

    const int tid  = threadIdx.x;
    const int warp = tid >> 5;
    const int lane = tid & 31;
    const int g    = lane >> 2;
    const int c    = lane & 3;
    const int wM   = warp & 3;      // 4 M-tiles of 16 rows
    const int wN   = warp >> 2;     // 4 N-groups

    const uint32_t smBase = (uint32_t)__cvta_generic_to_shared(smw);
    const uint32_t sKh  = smBase + SM_KH  * 4;
    const uint32_t sKl  = smBase + SM_KL  * 4;
    const uint32_t sVth = smBase + SM_VTH * 4;
    const uint32_t sVtl = smBase + SM_VTL * 4;
    const uint32_t sQh  = smBase + SM_QH  * 4;
    const uint32_t sQl  = smBase + SM_QL  * 4;
    const uint32_t sEP  = smBase + SM_EP  * 4;

    // ldmatrix lane offsets (uint units)
    const int aLdK = ((lane & 7) + 8 * ((lane >> 3) & 1)) * KSU + 4 * (lane >> 4);
    const int bLdK = ((lane & 7) + 8 * (lane >> 4)) * KSU + 4 * ((lane >> 3) & 1);
    const int bLdK2 = (lane & 7) * KSU + 4 * ((lane >> 3) & 1);
    const int aLdP = ((lane & 7) + 8 * ((lane >> 3) & 1)) * EPS + 4 * (lane >> 4);
    const int bLdV = ((lane & 7) + 8 * (lane >> 4)) * VSU + 4 * ((lane >> 3) & 1);

    // zero K/V region (pad rows/cols must be 0, not garbage)
    for (int i = tid; i < (SP * KSU * 2 + 64 * VSU * 2) / 4; i += 512)
        ((uint4*)smw)[i] = make_uint4(0u, 0u, 0u, 0u);
    __syncthreads();

    // K fill
    for (int t = tid; t < 197 * 8; t += 512) {
        int row = t >> 3, chk = t & 7;
        uint4 vh = *(const uint4*)(Kgh + row * 32 + chk * 4);
        uint4 vl = *(const uint4*)(Kgl + row * 32 + chk * 4);
        *(uint4*)(Kh + row * KSU + chk * 4) = vh;
        *(uint4*)(Kl + row * KSU + chk * 4) = vl;
    }
    // Vt fill (transpose + repack along j)
    for (int t = tid; t < 99 * 8; t += 512) {
        int j2 = t >> 3, dch = t & 7;
        int j0 = 2 * j2;
        uint4 ah = *(const uint4*)(Vgh + j0 * 32 + dch * 4);
        uint4 al = *(const uint4*)(Vgl + j0 * 32 + dch * 4);
        uint4 bhv = make_uint4(0u, 0u, 0u, 0u), blv = bhv;
        if (j0 + 1 < SEQ) {
            bhv = *(const uint4*)(Vgh + (j0 + 1) * 32 + dch * 4);
            blv = *(const uint4*)(Vgl + (j0 + 1) * 32 + dch * 4);
        }
        const unsigned* av[2] = {&ah.x, &al.x};
        const unsigned* bv[2] = {&bhv.x, &blv.x};
        unsigned* dst[2] = {Vth, Vtl};
        #pragma unroll
        for (int s = 0; s < 2; s++) {
            #pragma unroll
            for (int i = 0; i < 4; i++) {
                int d = dch * 8 + 2 * i;
                dst[s][(d    ) * VSU + j2] = prmt(av[s][i], bv[s][i], 0x5410);
                dst[s][(d + 1) * VSU + j2] = prmt(av[s][i], bv[s][i], 0x7632);
            }
        }
    }
    __syncthreads();

    for (int stripe = 0; stripe < 4; stripe++) {
        const int rbase = stripe * 64;

        // load Q stripe: 64 rows x 8 chunks, 512 threads -> 1 each
        {
            int row = tid >> 3, chk = tid & 7;
            int rg = rbase + row;
            uint4 vh = make_uint4(0u, 0u, 0u, 0u), vl = vh;
            if (rg < SEQ) {
                vh = *(const uint4*)(Qgh + rg * 32 + chk * 4);
                vl = *(const uint4*)(Qgl + rg * 32 + chk * 4);
            }
            *(uint4*)(Qh + row * KSU + chk * 4) = vh;
            *(uint4*)(Ql + row * KSU + chk * 4) = vl;
        }
        __syncthreads();

        // ---- E = Q_stripe @ K^T : warp tile 16 rows x 56 cols ----
        {
            float e[7][4];
            #pragma unroll
            for (int t = 0; t < 7; t++)
                #pragma unroll
                for (int r = 0; r < 4; r++) e[t][r] = 0.f;

            #pragma unroll
            for (int ks = 0; ks < 4; ks++) {
                const int kk = ks * 8;
                unsigned ah0, ah1, ah2, ah3, al0, al1, al2, al3;
                {
                    const uint32_t ao = (uint32_t)((wM * 16 * KSU + kk + aLdK) * 4);
                    ldsm4(ah0, ah1, ah2, ah3, sQh + ao);
                    ldsm4(al0, al1, al2, al3, sQl + ao);
                }
                unsigned bhf[7][2], blf[7][2];
                #pragma unroll
                for (int p = 0; p < 3; p++) {
                    const uint32_t bo = (uint32_t)(((wN * 56 + p * 16) * KSU + kk + bLdK) * 4);
                    ldsm4(bhf[2 * p][0], bhf[2 * p][1], bhf[2 * p + 1][0], bhf[2 * p + 1][1], sKh + bo);
                    ldsm4(blf[2 * p][0], blf[2 * p][1], blf[2 * p + 1][0], blf[2 * p + 1][1], sKl + bo);
                }
                {
                    const uint32_t bo = (uint32_t)(((wN * 56 + 48) * KSU + kk + bLdK2) * 4);
                    ldsm2(bhf[6][0], bhf[6][1], sKh + bo);
                    ldsm2(blf[6][0], blf[6][1], sKl + bo);
                }
                #pragma unroll
                for (int t = 0; t < 7; t++) {
                    mma_bf16(e[t][0], e[t][1], e[t][2], e[t][3],
                             ah0, ah1, ah2, ah3, bhf[t][0], bhf[t][1]);
                    mma_bf16(e[t][0], e[t][1], e[t][2], e[t][3],
                             ah0, ah1, ah2, ah3, blf[t][0], blf[t][1]);
                    mma_bf16(e[t][0], e[t][1], e[t][2], e[t][3],
                             al0, al1, al2, al3, bhf[t][0], bhf[t][1]);
                }
            }
            #pragma unroll
            for (int t = 0; t < 7; t++) {
                const int col = wN * 56 + t * 8 + 2 * c;
                const int row = wM * 16 + g;
                *(float2*)(E + row * EPS + col)       = make_float2(e[t][0], e[t][1]);
                *(float2*)(E + (row + 8) * EPS + col) = make_float2(e[t][2], e[t][3]);
            }
        }
        __syncthreads();

        // ---- softmax rows (warp w owns rows 4w..4w+3); P overwrites E ----
        {
            #pragma unroll
            for (int rr = 0; rr < 4; rr++) {
                const int row = warp * 4 + rr;
                const float* er = E + row * EPS;
                float e0[4], e1[4];
                float mx = -1e30f;
                int cnt = 0;
                for (int p2 = lane; p2 < 112; p2 += 32, cnt++) {
                    float2 ev = *(const float2*)(er + 2 * p2);
                    e0[cnt] = (2 * p2     < SEQ) ? ev.x : -1e30f;
                    e1[cnt] = (2 * p2 + 1 < SEQ) ? ev.y : -1e30f;
                    mx = fmaxf(mx, fmaxf(e0[cnt], e1[cnt]));
                }
                #pragma unroll
                for (int o = 16; o > 0; o >>= 1)
                    mx = fmaxf(mx, __shfl_xor_sync(0xffffffffu, mx, o));
                float sum = 0.f;
                #pragma unroll
                for (int i = 0; i < 4; i++) {
                    if (i < cnt) {
                        e0[i] = __expf(e0[i] - mx);
                        e1[i] = __expf(e1[i] - mx);
                        sum += e0[i] + e1[i];
                    }
                }
                #pragma unroll
                for (int o = 16; o > 0; o >>= 1)
                    sum += __shfl_xor_sync(0xffffffffu, sum, o);
                // All lanes' E reads for this row completed before this point
                // (shfl reductions are warp-synchronous) -> safe to overwrite.
                const float inv = 1.0f / (sum * 27.712812921102035f);  // sqrt(768)
                cnt = 0;
                for (int p2 = lane; p2 < 112; p2 += 32, cnt++) {
                    float p0 = e0[cnt] * inv;
                    float p1 = e1[cnt] * inv;
                    float h0 = __bfloat162float(__float2bfloat16(p0));
                    float h1 = __bfloat162float(__float2bfloat16(p1));
                    Pu[row * EPS + p2]         = pack_hi2(p0, p1);
                    Pu[row * EPS + PLOFF + p2] = pack_hi2(p0 - h0, p1 - h1);
                }
            }
        }
        __syncthreads();

        // ---- O = P @ V : warp tile 16 rows x 16 cols ----
        {
            float o[2][4];
            #pragma unroll
            for (int t = 0; t < 2; t++)
                #pragma unroll
                for (int r = 0; r < 4; r++) o[t][r] = 0.f;

            #pragma unroll 2
            for (int ks = 0; ks < 14; ks++) {
                const int kk = ks * 8;
                unsigned ah0, ah1, ah2, ah3, al0, al1, al2, al3;
                {
                    const uint32_t ao = (uint32_t)((wM * 16 * EPS + kk + aLdP) * 4);
                    ldsm4(ah0, ah1, ah2, ah3, sEP + ao);
                    ldsm4(al0, al1, al2, al3, sEP + ao + PLOFF * 4);
                }
                unsigned bhf[2][2], blf[2][2];
                {
                    const uint32_t bo = (uint32_t)((wN * 16 * VSU + kk + bLdV) * 4);
                    ldsm4(bhf[0][0], bhf[0][1], bhf[1][0], bhf[1][1], sVth + bo);
                    ldsm4(blf[0][0], blf[0][1], blf[1][0], blf[1][1], sVtl + bo);
                }
                #pragma unroll
                for (int t = 0; t < 2; t++) {
                    mma_bf16(o[t][0], o[t][1], o[t][2], o[t][3],
                             ah0, ah1, ah2, ah3, bhf[t][0], bhf[t][1]);
                    mma_bf16(o[t][0], o[t][1], o[t][2], o[t][3],
                             ah0, ah1, ah2, ah3, blf[t][0], blf[t][1]);
                    mma_bf16(o[t][0], o[t][1], o[t][2], o[t][3],
                             al0, al1, al2, al3, bhf[t][0], bhf[t][1]);
                }
            }
            #pragma unroll
            for (int t = 0; t < 2; t++) {
                const int col = wN * 16 + t * 8 + 2 * c;
                const int rg0 = rbase + wM * 16 + g;
                const int rg1 = rg0 + 8;
                if (rg0 < SEQ) {
                    float h0 = __bfloat162float(__float2bfloat16(o[t][0]));
                    float h1 = __bfloat162float(__float2bfloat16(o[t][1]));
                    AOh[(rg0 * HD + col) >> 1] = pack_hi2(o[t][0], o[t][1]);
                    AOl[(rg0 * HD + col) >> 1] = pack_hi2(o[t][0] - h0, o[t][1] - h1);
                }
                if (rg1 < SEQ) {
                    float h0 = __bfloat162float(__float2bfloat16(o[t][2]));
                    float h1 = __bfloat162float(__float2bfloat16(o[t][3]));
                    AOh[(rg1 * HD + col) >> 1] = pack_hi2(o[t][2], o[t][3]);
                    AOl[(rg1 * HD + col) >> 1] = pack_hi2(o[t][2] - h0, o[t][3] - h1);
                }
            }
        }
        __syncthreads();
    }
}

// ---------------------------------------------------------------------------
// Launch
// ---------------------------------------------------------------------------
extern "C" void kernel_launch(void* const* d_in, const int* in_sizes, int n_in,
                              void* d_out, int out_size)
{
    const float* x  = (const float*)d_in[0];
    const float* Wq = (const float*)d_in[1];
    const float* bq = (const float*)d_in[2];
    const float* Wk = (const float*)d_in[3];
    const float* bk = (const float*)d_in[4];
    const float* Wv = (const float*)d_in[5];
    const float* bv = (const float*)d_in[6];
    const float* Wp = (const float*)d_in[7];
    const float* bp = (const float*)d_in[8];
    float* out = (float*)d_out;

    cudaFuncSetAttribute(qkv_gemm_kernel,
                         cudaFuncAttributeMaxDynamicSharedMemorySize,
                         GEMM_SMEM_BYTES);
    cudaFuncSetAttribute(proj_gemm_kernel,
                         cudaFuncAttributeMaxDynamicSharedMemorySize,
                         GEMM_SMEM_BYTES);
    cudaFuncSetAttribute(attn_kernel,
                         cudaFuncAttributeMaxDynamicSharedMemorySize,
                         ATTN_SMEM_BYTES);

    const int n4x = MROWS * EDIM / 4;
    const int n4w = EDIM * EDIM / 4;
    split_x_kernel<<<(n4x + 255) / 256, 256>>>(x, n4x);
    dim3 gridW((n4w + 255) / 256, 1, 4);
    split_w_kernel<<<gridW, 256>>>(Wq, Wk, Wv, Wp, n4w);

    dim3 gridQKV(EDIM / 128, (MROWS + 127) / 128, 3);   // (6, 99, 3)
    qkv_gemm_kernel<<<gridQKV, 256, GEMM_SMEM_BYTES>>>(bq, bk, bv);

    attn_kernel<<<BATCH * NH, 512, ATTN_SMEM_BYTES>>>();

    dim3 gridP(EDIM / 128, (MROWS + 127) / 128, 1);     // (6, 99)
    proj_gemm_kernel<<<gridP, 256, GEMM_SMEM_BYTES>>>(bp, out);
}